// round 1
// baseline (speedup 1.0000x reference)
#include <cuda_runtime.h>
#include <cuda_pipeline.h>
#include <math.h>

// ---------------- problem constants ----------------
#define BATCH   4
#define SEQ     2048
#define DMODEL  768
#define NHEADS  12
#define DK      64
#define DFF     3072
#define MROWS   (BATCH*SEQ)          // 8192
#define EPS_LN  1e-6f
#define NEGINF  -1.0e9f

// ---------------- scratch (device globals; allocation-free) ----------------
__device__ float g_xn [MROWS*DMODEL];
__device__ float g_q  [MROWS*DMODEL];
__device__ float g_k  [MROWS*DMODEL];
__device__ float g_v  [MROWS*DMODEL];
__device__ float g_ctx[MROWS*DMODEL];
__device__ float g_x2 [MROWS*DMODEL];
__device__ float g_h  [MROWS*DFF];

// =====================================================================
// LayerNorm: custom — mean, var with ddof=1, out = a*(x-mean)/(eps+std)+b
// one row (768) per block, 256 threads
// =====================================================================
__device__ __forceinline__ float block_sum_256(float v, float* red) {
    #pragma unroll
    for (int off = 16; off; off >>= 1) v += __shfl_xor_sync(0xffffffffu, v, off);
    int t = threadIdx.x;
    if ((t & 31) == 0) red[t >> 5] = v;
    __syncthreads();
    float s = 0.f;
    #pragma unroll
    for (int w = 0; w < 8; w++) s += red[w];
    __syncthreads();
    return s;
}

__global__ void __launch_bounds__(256) ln_kernel(
    const float* __restrict__ x, float* __restrict__ o,
    const float* __restrict__ ga, const float* __restrict__ gb)
{
    __shared__ float red[8];
    int row = blockIdx.x;
    int t = threadIdx.x;
    const float* xr = x + (size_t)row * DMODEL;
    float v0 = xr[t], v1 = xr[t + 256], v2 = xr[t + 512];
    float mean = block_sum_256(v0 + v1 + v2, red) * (1.0f / 768.0f);
    float d0 = v0 - mean, d1 = v1 - mean, d2 = v2 - mean;
    float ss = block_sum_256(d0*d0 + d1*d1 + d2*d2, red);
    float stdv = sqrtf(ss * (1.0f / 767.0f));      // ddof = 1
    float sc = ga[0] / (EPS_LN + stdv);
    float bb = gb[0];
    float* orow = o + (size_t)row * DMODEL;
    orow[t]       = d0 * sc + bb;
    orow[t + 256] = d1 * sc + bb;
    orow[t + 512] = d2 * sc + bb;
}

// =====================================================================
// Generic SGEMM: C = epilogue(A[M,K] @ B[K,N] + bias), 128x128x16 tiles,
// 256 threads, 8x8 per-thread microtile, 2-stage cp.async pipeline.
// =====================================================================
#define BM 128
#define BN 128
#define BK 16
#define TM 8
#define TN 8

#define EPI_BIAS 0
#define EPI_RELU 1
#define EPI_RES  2
#define EPI_QKV  3   // write to [B,H,S,DK] layout

__global__ void __launch_bounds__(256) sgemm_kernel(
    const float* __restrict__ A, const float* __restrict__ B,
    const float* __restrict__ bias, const float* __restrict__ res,
    float* __restrict__ C, int M, int N, int K, int epi)
{
    __shared__ float As[2][BM][BK];   // [m][k]
    __shared__ float Bs[2][BK][BN];   // [k][n]

    int tid  = threadIdx.x;
    int m0   = blockIdx.y * BM;
    int n0   = blockIdx.x * BN;
    int trow = tid >> 4;      // 0..15
    int tcol = tid & 15;      // 0..15

    // each thread copies 2 float4 chunks of A and 2 of B per stage
    int cbase = tid * 2;

    auto loadA = [&](int stage, int k0) {
        #pragma unroll
        for (int i = 0; i < 2; i++) {
            int c = cbase + i;
            int r = c >> 2, c4 = (c & 3) << 2;      // 128 rows x 4 chunks
            __pipeline_memcpy_async(&As[stage][r][c4],
                                    &A[(size_t)(m0 + r) * K + k0 + c4], 16);
        }
    };
    auto loadB = [&](int stage, int k0) {
        #pragma unroll
        for (int i = 0; i < 2; i++) {
            int c = cbase + i;
            int r = c >> 5, c4 = (c & 31) << 2;     // 16 rows x 32 chunks
            __pipeline_memcpy_async(&Bs[stage][r][c4],
                                    &B[(size_t)(k0 + r) * N + n0 + c4], 16);
        }
    };

    float acc[TM][TN];
    #pragma unroll
    for (int i = 0; i < TM; i++)
        #pragma unroll
        for (int j = 0; j < TN; j++) acc[i][j] = 0.f;

    int nT = K / BK;
    loadA(0, 0); loadB(0, 0); __pipeline_commit();

    for (int t = 0; t < nT; ++t) {
        if (t + 1 < nT) {
            loadA((t + 1) & 1, (t + 1) * BK);
            loadB((t + 1) & 1, (t + 1) * BK);
            __pipeline_commit();
            __pipeline_wait_prior(1);
        } else {
            __pipeline_wait_prior(0);
        }
        __syncthreads();
        int s = t & 1;
        #pragma unroll
        for (int k = 0; k < BK; k++) {
            float a[TM], b[TN];
            #pragma unroll
            for (int i = 0; i < TM; i++) a[i] = As[s][trow * TM + i][k];
            #pragma unroll
            for (int j = 0; j < TN; j += 4)
                *(float4*)&b[j] = *(const float4*)&Bs[s][k][tcol * TN + j];
            #pragma unroll
            for (int i = 0; i < TM; i++)
                #pragma unroll
                for (int j = 0; j < TN; j++) acc[i][j] += a[i] * b[j];
        }
        __syncthreads();
    }

    // ----- epilogue -----
    #pragma unroll
    for (int i = 0; i < TM; i++) {
        int row = m0 + trow * TM + i;
        #pragma unroll
        for (int j = 0; j < TN; j += 4) {
            int col = n0 + tcol * TN + j;
            float4 bv = *(const float4*)&bias[col];
            float4 v;
            v.x = acc[i][j]     + bv.x;
            v.y = acc[i][j + 1] + bv.y;
            v.z = acc[i][j + 2] + bv.z;
            v.w = acc[i][j + 3] + bv.w;
            if (epi == EPI_RELU) {
                v.x = fmaxf(v.x, 0.f); v.y = fmaxf(v.y, 0.f);
                v.z = fmaxf(v.z, 0.f); v.w = fmaxf(v.w, 0.f);
            } else if (epi == EPI_RES) {
                float4 r4 = *(const float4*)&res[(size_t)row * N + col];
                v.x += r4.x; v.y += r4.y; v.z += r4.z; v.w += r4.w;
            }
            if (epi == EPI_QKV) {
                int b_ = row >> 11, s_ = row & 2047;
                int h_ = col >> 6,  d_ = col & 63;
                size_t oidx = (((size_t)(b_ * NHEADS + h_) * SEQ + s_) << 6) + d_;
                *(float4*)&C[oidx] = v;
            } else {
                *(float4*)&C[(size_t)row * N + col] = v;
            }
        }
    }
}

// =====================================================================
// Flash-style attention, fp32. Q/K/V laid out [B*H, S, DK].
// Block: 256 threads, BQ=128 q rows, BKV=64 kv per tile.
// Thread (ty,tx): ty=tid/16 owns 8 q rows, tx=tid%16 owns 4 cols.
// smem: sQ[128][64], sKt[64(d)][64(kv)], sV[64][64], sP[128][65]
// =====================================================================
#define BQ  128
#define BKV 64
#define ATTN_SMEM_FLOATS (BQ*DK + DK*BKV + BKV*DK + BQ*65)
#define ATTN_SMEM_BYTES  (ATTN_SMEM_FLOATS * 4)

__global__ void __launch_bounds__(256) attn_kernel(
    const float* __restrict__ Q, const float* __restrict__ K,
    const float* __restrict__ V, const int* __restrict__ mask,
    float* __restrict__ ctx)
{
    extern __shared__ float sm[];
    float* sQ  = sm;                    // [128][64]
    float* sKt = sQ  + BQ * DK;         // [d=64][kv=64]  (transposed)
    float* sV  = sKt + DK * BKV;        // [kv=64][d=64]
    float* sP  = sV  + BKV * DK;        // [128][65]

    int tid = threadIdx.x;
    int bh  = blockIdx.y;               // 0..47
    int q0  = blockIdx.x * BQ;
    int b   = bh / NHEADS;
    int h   = bh % NHEADS;

    const float* Qh = Q + (size_t)bh * SEQ * DK;
    const float* Kh = K + (size_t)bh * SEQ * DK;
    const float* Vh = V + (size_t)bh * SEQ * DK;
    const int* mrow = mask + b * SEQ;

    // load Q tile: 8192 floats = 2048 float4 / 256 thr = 8 each
    #pragma unroll
    for (int i = 0; i < 8; i++) {
        int c = tid + 256 * i;
        int r = c >> 4, c4 = (c & 15) << 2;
        *(float4*)&sQ[r * DK + c4] =
            *(const float4*)&Qh[(size_t)(q0 + r) * DK + c4];
    }

    int ty = tid >> 4, tx = tid & 15;
    float m_[8], l_[8], acc[8][4];
    #pragma unroll
    for (int i = 0; i < 8; i++) {
        m_[i] = -1e30f; l_[i] = 0.f;
        #pragma unroll
        for (int j = 0; j < 4; j++) acc[i][j] = 0.f;
    }
    __syncthreads();

    for (int kv0 = 0; kv0 < SEQ; kv0 += BKV) {
        // load K (transposed -> sKt[d][kv]) and V (natural): 4 float4 each
        #pragma unroll
        for (int i = 0; i < 4; i++) {
            int c = tid + 256 * i;
            int r = c >> 4, c4 = (c & 15) << 2;
            float4 kq = *(const float4*)&Kh[(size_t)(kv0 + r) * DK + c4];
            sKt[(c4 + 0) * BKV + r] = kq.x;
            sKt[(c4 + 1) * BKV + r] = kq.y;
            sKt[(c4 + 2) * BKV + r] = kq.z;
            sKt[(c4 + 3) * BKV + r] = kq.w;
            *(float4*)&sV[r * DK + c4] =
                *(const float4*)&Vh[(size_t)(kv0 + r) * DK + c4];
        }
        __syncthreads();

        // S = Q @ K^T  (tile 128x64), per-thread 8x4
        float s_[8][4];
        #pragma unroll
        for (int i = 0; i < 8; i++)
            #pragma unroll
            for (int j = 0; j < 4; j++) s_[i][j] = 0.f;

        #pragma unroll 8
        for (int kk = 0; kk < DK; kk++) {
            float a[8], bb[4];
            #pragma unroll
            for (int i = 0; i < 8; i++) a[i] = sQ[(ty * 8 + i) * DK + kk];
            *(float4*)bb = *(const float4*)&sKt[kk * BKV + tx * 4];
            #pragma unroll
            for (int i = 0; i < 8; i++)
                #pragma unroll
                for (int j = 0; j < 4; j++) s_[i][j] += a[i] * bb[j];
        }

        // scale + mask
        int mv[4];
        #pragma unroll
        for (int j = 0; j < 4; j++) mv[j] = mrow[kv0 + tx * 4 + j];
        #pragma unroll
        for (int i = 0; i < 8; i++)
            #pragma unroll
            for (int j = 0; j < 4; j++)
                s_[i][j] = (mv[j] == 0) ? NEGINF : s_[i][j] * 0.125f;

        // online softmax (row groups = 16 threads sharing ty)
        #pragma unroll
        for (int i = 0; i < 8; i++) {
            float mx = fmaxf(fmaxf(s_[i][0], s_[i][1]), fmaxf(s_[i][2], s_[i][3]));
            #pragma unroll
            for (int off = 8; off; off >>= 1)
                mx = fmaxf(mx, __shfl_xor_sync(0xffffffffu, mx, off, 16));
            float mn = fmaxf(m_[i], mx);
            float corr = __expf(m_[i] - mn);
            float ls = 0.f;
            #pragma unroll
            for (int j = 0; j < 4; j++) {
                float p = __expf(s_[i][j] - mn);
                sP[(ty * 8 + i) * 65 + tx * 4 + j] = p;
                ls += p;
            }
            #pragma unroll
            for (int off = 8; off; off >>= 1)
                ls += __shfl_xor_sync(0xffffffffu, ls, off, 16);
            l_[i] = l_[i] * corr + ls;
            m_[i] = mn;
            #pragma unroll
            for (int j = 0; j < 4; j++) acc[i][j] *= corr;
        }
        __syncthreads();

        // O += P @ V
        #pragma unroll 8
        for (int kk = 0; kk < BKV; kk++) {
            float a[8], bb[4];
            #pragma unroll
            for (int i = 0; i < 8; i++) a[i] = sP[(ty * 8 + i) * 65 + kk];
            *(float4*)bb = *(const float4*)&sV[kk * DK + tx * 4];
            #pragma unroll
            for (int i = 0; i < 8; i++)
                #pragma unroll
                for (int j = 0; j < 4; j++) acc[i][j] += a[i] * bb[j];
        }
        __syncthreads();
    }

    // write ctx in [B,S,DMODEL] layout (col = h*64 + d)
    #pragma unroll
    for (int i = 0; i < 8; i++) {
        float inv = 1.0f / l_[i];
        int row = b * SEQ + q0 + ty * 8 + i;
        float4 v;
        v.x = acc[i][0] * inv; v.y = acc[i][1] * inv;
        v.z = acc[i][2] * inv; v.w = acc[i][3] * inv;
        *(float4*)&ctx[(size_t)row * DMODEL + h * DK + tx * 4] = v;
    }
}

// =====================================================================
// launcher
// =====================================================================
extern "C" void kernel_launch(void* const* d_in, const int* in_sizes, int n_in,
                              void* d_out, int out_size)
{
    const float* x    = (const float*)d_in[0];
    const int*   mask = (const int*)  d_in[1];
    const float* wq = (const float*)d_in[2],  *bq = (const float*)d_in[3];
    const float* wk = (const float*)d_in[4],  *bk = (const float*)d_in[5];
    const float* wv = (const float*)d_in[6],  *bv = (const float*)d_in[7];
    const float* wo = (const float*)d_in[8],  *bo = (const float*)d_in[9];
    const float* w1 = (const float*)d_in[10], *b1 = (const float*)d_in[11];
    const float* w2 = (const float*)d_in[12], *b2 = (const float*)d_in[13];
    const float* ln1a = (const float*)d_in[14], *ln1b = (const float*)d_in[15];
    const float* ln2a = (const float*)d_in[16], *ln2b = (const float*)d_in[17];
    float* out = (float*)d_out;

    float *xn, *q, *k, *v, *ctx, *x2, *hbuf;
    cudaGetSymbolAddress((void**)&xn,   g_xn);
    cudaGetSymbolAddress((void**)&q,    g_q);
    cudaGetSymbolAddress((void**)&k,    g_k);
    cudaGetSymbolAddress((void**)&v,    g_v);
    cudaGetSymbolAddress((void**)&ctx,  g_ctx);
    cudaGetSymbolAddress((void**)&x2,   g_x2);
    cudaGetSymbolAddress((void**)&hbuf, g_h);

    cudaFuncSetAttribute(attn_kernel,
                         cudaFuncAttributeMaxDynamicSharedMemorySize,
                         ATTN_SMEM_BYTES);

    dim3 g768 (DMODEL / BN, MROWS / BM);   // (6, 64)
    dim3 g3072(DFF   / BN, MROWS / BM);    // (24, 64)

    // sublayer 1
    ln_kernel<<<MROWS, 256>>>(x, xn, ln1a, ln1b);
    sgemm_kernel<<<g768, 256>>>(xn, wq, bq, nullptr, q, MROWS, DMODEL, DMODEL, EPI_QKV);
    sgemm_kernel<<<g768, 256>>>(xn, wk, bk, nullptr, k, MROWS, DMODEL, DMODEL, EPI_QKV);
    sgemm_kernel<<<g768, 256>>>(xn, wv, bv, nullptr, v, MROWS, DMODEL, DMODEL, EPI_QKV);
    attn_kernel<<<dim3(SEQ / BQ, BATCH * NHEADS), 256, ATTN_SMEM_BYTES>>>(q, k, v, mask, ctx);
    sgemm_kernel<<<g768, 256>>>(ctx, wo, bo, x, x2, MROWS, DMODEL, DMODEL, EPI_RES);

    // sublayer 2
    ln_kernel<<<MROWS, 256>>>(x2, xn, ln2a, ln2b);
    sgemm_kernel<<<g3072, 256>>>(xn, w1, b1, nullptr, hbuf, MROWS, DFF, DMODEL, EPI_RELU);
    sgemm_kernel<<<g768, 256>>>(hbuf, w2, b2, x2, out, MROWS, DMODEL, DFF, EPI_RES);
}

// round 4
// speedup vs baseline: 1.6433x; 1.6433x over previous
#include <cuda_runtime.h>
#include <cuda_pipeline.h>
#include <math.h>
#include <cstdint>

// ---------------- problem constants ----------------
#define BATCH   4
#define SEQ     2048
#define DMODEL  768
#define NHEADS  12
#define DK      64
#define DFF     3072
#define MROWS   (BATCH*SEQ)          // 8192
#define EPS_LN  1e-6f
#define NEGINF  -1.0e9f

// ---------------- scratch (device globals; allocation-free) ----------------
__device__ float g_xn [MROWS*DMODEL];
__device__ float g_q  [MROWS*DMODEL];
__device__ float g_k  [MROWS*DMODEL];
__device__ float g_v  [MROWS*DMODEL];
__device__ float g_ctx[MROWS*DMODEL];
__device__ float g_x2 [MROWS*DMODEL];
__device__ float g_h  [MROWS*DFF];
// tf32-rounded weight copies (same [K,N] layout as inputs)
__device__ float g_wqr[DMODEL*DMODEL];
__device__ float g_wkr[DMODEL*DMODEL];
__device__ float g_wvr[DMODEL*DMODEL];
__device__ float g_wor[DMODEL*DMODEL];
__device__ float g_w1r[DMODEL*DFF];
__device__ float g_w2r[DFF*DMODEL];

// ---------------- helpers ----------------
__device__ __forceinline__ float tf32r(float x) {
    uint32_t y;                                    // tf32 dst must be .b32
    asm("cvt.rna.tf32.f32 %0, %1;" : "=r"(y) : "f"(x));
    return __uint_as_float(y);
}

__device__ __forceinline__ void mma_tf32(float* d,
    uint32_t a0, uint32_t a1, uint32_t a2, uint32_t a3,
    uint32_t b0, uint32_t b1)
{
    asm volatile(
        "mma.sync.aligned.m16n8k8.row.col.f32.tf32.tf32.f32 "
        "{%0,%1,%2,%3}, {%4,%5,%6,%7}, {%8,%9}, {%0,%1,%2,%3};"
        : "+f"(d[0]), "+f"(d[1]), "+f"(d[2]), "+f"(d[3])
        : "r"(a0), "r"(a1), "r"(a2), "r"(a3), "r"(b0), "r"(b1));
}

// =====================================================================
// tf32 truncate-copy for weights
// =====================================================================
__global__ void __launch_bounds__(256) trunc_kernel(
    const float* __restrict__ W, float* __restrict__ Wr, int n4)
{
    int i = blockIdx.x * 256 + threadIdx.x;
    if (i < n4) {
        float4 v = ((const float4*)W)[i];
        v.x = tf32r(v.x); v.y = tf32r(v.y);
        v.z = tf32r(v.z); v.w = tf32r(v.w);
        ((float4*)Wr)[i] = v;
    }
}

// =====================================================================
// LayerNorm (tf32-rounds its output — it feeds GEMM A operands)
// =====================================================================
__device__ __forceinline__ float block_sum_256(float v, float* red) {
    #pragma unroll
    for (int off = 16; off; off >>= 1) v += __shfl_xor_sync(0xffffffffu, v, off);
    int t = threadIdx.x;
    if ((t & 31) == 0) red[t >> 5] = v;
    __syncthreads();
    float s = 0.f;
    #pragma unroll
    for (int w = 0; w < 8; w++) s += red[w];
    __syncthreads();
    return s;
}

__global__ void __launch_bounds__(256) ln_kernel(
    const float* __restrict__ x, float* __restrict__ o,
    const float* __restrict__ ga, const float* __restrict__ gb)
{
    __shared__ float red[8];
    int row = blockIdx.x;
    int t = threadIdx.x;
    const float* xr = x + (size_t)row * DMODEL;
    float v0 = xr[t], v1 = xr[t + 256], v2 = xr[t + 512];
    float mean = block_sum_256(v0 + v1 + v2, red) * (1.0f / 768.0f);
    float d0 = v0 - mean, d1 = v1 - mean, d2 = v2 - mean;
    float ss = block_sum_256(d0*d0 + d1*d1 + d2*d2, red);
    float stdv = sqrtf(ss * (1.0f / 767.0f));      // ddof = 1
    float sc = ga[0] / (EPS_LN + stdv);
    float bb = gb[0];
    float* orow = o + (size_t)row * DMODEL;
    orow[t]       = tf32r(d0 * sc + bb);
    orow[t + 256] = tf32r(d1 * sc + bb);
    orow[t + 512] = tf32r(d2 * sc + bb);
}

// =====================================================================
// tf32 mma.sync GEMM: C = epi(A[M,K] @ W[K,N] + bias)
// CTA 128x128, BK=16, 4-stage cp.async, 8 warps (2M x 4N), warp 64x32.
// A smem [m][k] stride 20 (conflict-free frag loads: bank=20g+q)
// B smem [k][n] stride 136 (bank=8q+g), loaded straight from W[K,N].
// =====================================================================
#define EPI_BIAS 0
#define EPI_RELU 1
#define EPI_RES  2
#define EPI_QKV  3

#define BM 128
#define BN 128
#define BKT 16
#define STG 4
#define APAD 20
#define BPAD 136
#define A_STG (BM*APAD)                 // 2560 floats
#define B_STG (BKT*BPAD)                // 2176 floats
#define GEMM_SMEM ((STG*(A_STG+B_STG))*4)   // 75776 B

__global__ void __launch_bounds__(256) mma_gemm_kernel(
    const float* __restrict__ A, const float* __restrict__ B,
    const float* __restrict__ bias, const float* __restrict__ res,
    float* __restrict__ C, int M, int N, int K, int epi)
{
    extern __shared__ float sm[];
    float* As = sm;                     // [STG][BM][APAD]
    float* Bs = sm + STG * A_STG;       // [STG][BKT][BPAD]

    int tid = threadIdx.x;
    int wid = tid >> 5, lane = tid & 31;
    int g = lane >> 2, q = lane & 3;
    int wm = (wid >> 2) * 64;           // warp M offset (0/64)
    int wn = (wid & 3) * 32;            // warp N offset (0..96)
    int m0 = blockIdx.y * BM, n0 = blockIdx.x * BN;

    const float* Ab = A + (size_t)m0 * K;
    const float* Bb = B + n0;

    auto load_stage = [&](int st, int k0) {
        float* aS = As + st * A_STG;
        float* bS = Bs + st * B_STG;
        #pragma unroll
        for (int i = 0; i < 8; i++) {           // A: 2048 floats, 4B each
            int e = tid + (i << 8);
            int m = e >> 4, k = e & 15;
            __pipeline_memcpy_async(aS + m * APAD + k,
                                    Ab + (size_t)m * K + k0 + k, 4);
        }
        #pragma unroll
        for (int i = 0; i < 2; i++) {           // B: 512 float4 chunks
            int c = tid + (i << 8);
            int k = c >> 5, n4 = (c & 31) << 2;
            __pipeline_memcpy_async(bS + k * BPAD + n4,
                                    Bb + (size_t)(k0 + k) * N + n4, 16);
        }
    };

    float acc[4][4][4];
    #pragma unroll
    for (int mt = 0; mt < 4; mt++)
        #pragma unroll
        for (int nt = 0; nt < 4; nt++)
            #pragma unroll
            for (int c = 0; c < 4; c++) acc[mt][nt][c] = 0.f;

    int nT = K >> 4;
    #pragma unroll
    for (int s = 0; s < STG - 1; s++) {
        load_stage(s, s << 4);
        __pipeline_commit();
    }

    for (int t = 0; t < nT; t++) {
        __pipeline_wait_prior(STG - 2);
        __syncthreads();
        int nx = t + STG - 1;
        if (nx < nT) load_stage(nx & (STG - 1), nx << 4);
        __pipeline_commit();

        int st = t & (STG - 1);
        const float* aS = As + st * A_STG;
        const float* bS = Bs + st * B_STG;

        #pragma unroll
        for (int kk = 0; kk < BKT; kk += 8) {
            uint32_t af[4][4], bf[4][2];
            #pragma unroll
            for (int mt = 0; mt < 4; mt++) {
                const float* ap = aS + (wm + mt * 16 + g) * APAD + kk + q;
                af[mt][0] = __float_as_uint(ap[0]);
                af[mt][1] = __float_as_uint(ap[8 * APAD]);
                af[mt][2] = __float_as_uint(ap[4]);
                af[mt][3] = __float_as_uint(ap[8 * APAD + 4]);
            }
            #pragma unroll
            for (int nt = 0; nt < 4; nt++) {
                const float* bp = bS + (kk + q) * BPAD + wn + nt * 8 + g;
                bf[nt][0] = __float_as_uint(bp[0]);
                bf[nt][1] = __float_as_uint(bp[4 * BPAD]);
            }
            #pragma unroll
            for (int mt = 0; mt < 4; mt++)
                #pragma unroll
                for (int nt = 0; nt < 4; nt++)
                    mma_tf32(acc[mt][nt], af[mt][0], af[mt][1], af[mt][2], af[mt][3],
                             bf[nt][0], bf[nt][1]);
        }
    }

    // ----- epilogue (register accumulators -> gmem) -----
    #pragma unroll
    for (int mt = 0; mt < 4; mt++) {
        #pragma unroll
        for (int half = 0; half < 2; half++) {
            int row = m0 + wm + mt * 16 + g + half * 8;
            #pragma unroll
            for (int nt = 0; nt < 4; nt++) {
                int col = n0 + wn + nt * 8 + 2 * q;
                float c0 = acc[mt][nt][half * 2 + 0];
                float c1 = acc[mt][nt][half * 2 + 1];
                float2 bv = *(const float2*)&bias[col];
                c0 += bv.x; c1 += bv.y;
                if (epi == EPI_RELU) {
                    c0 = tf32r(fmaxf(c0, 0.f));   // feeds next GEMM A side
                    c1 = tf32r(fmaxf(c1, 0.f));
                } else if (epi == EPI_RES) {
                    float2 r2 = *(const float2*)&res[(size_t)row * N + col];
                    c0 += r2.x; c1 += r2.y;
                }
                if (epi == EPI_QKV) {
                    int b_ = row >> 11, s_ = row & 2047;
                    int h_ = col >> 6,  d_ = col & 63;
                    size_t o = (((size_t)(b_ * NHEADS + h_) * SEQ + s_) << 6) + d_;
                    *(float2*)&C[o] = make_float2(c0, c1);
                } else {
                    *(float2*)&C[(size_t)row * N + col] = make_float2(c0, c1);
                }
            }
        }
    }
}

// =====================================================================
// Flash-style attention, fp32 (ctx store tf32-rounded: feeds wo GEMM)
// =====================================================================
#define BQ  128
#define BKV 64
#define ATTN_SMEM_FLOATS (BQ*DK + DK*BKV + BKV*DK + BQ*65)
#define ATTN_SMEM_BYTES  (ATTN_SMEM_FLOATS * 4)

__global__ void __launch_bounds__(256) attn_kernel(
    const float* __restrict__ Q, const float* __restrict__ K,
    const float* __restrict__ V, const int* __restrict__ mask,
    float* __restrict__ ctx)
{
    extern __shared__ float smf[];
    float* sQ  = smf;
    float* sKt = sQ  + BQ * DK;
    float* sV  = sKt + DK * BKV;
    float* sP  = sV  + BKV * DK;

    int tid = threadIdx.x;
    int bh  = blockIdx.y;
    int q0  = blockIdx.x * BQ;
    int b   = bh / NHEADS;
    int h   = bh % NHEADS;

    const float* Qh = Q + (size_t)bh * SEQ * DK;
    const float* Kh = K + (size_t)bh * SEQ * DK;
    const float* Vh = V + (size_t)bh * SEQ * DK;
    const int* mrow = mask + b * SEQ;

    #pragma unroll
    for (int i = 0; i < 8; i++) {
        int c = tid + 256 * i;
        int r = c >> 4, c4 = (c & 15) << 2;
        *(float4*)&sQ[r * DK + c4] =
            *(const float4*)&Qh[(size_t)(q0 + r) * DK + c4];
    }

    int ty = tid >> 4, tx = tid & 15;
    float m_[8], l_[8], acc[8][4];
    #pragma unroll
    for (int i = 0; i < 8; i++) {
        m_[i] = -1e30f; l_[i] = 0.f;
        #pragma unroll
        for (int j = 0; j < 4; j++) acc[i][j] = 0.f;
    }
    __syncthreads();

    for (int kv0 = 0; kv0 < SEQ; kv0 += BKV) {
        #pragma unroll
        for (int i = 0; i < 4; i++) {
            int c = tid + 256 * i;
            int r = c >> 4, c4 = (c & 15) << 2;
            float4 kq = *(const float4*)&Kh[(size_t)(kv0 + r) * DK + c4];
            sKt[(c4 + 0) * BKV + r] = kq.x;
            sKt[(c4 + 1) * BKV + r] = kq.y;
            sKt[(c4 + 2) * BKV + r] = kq.z;
            sKt[(c4 + 3) * BKV + r] = kq.w;
            *(float4*)&sV[r * DK + c4] =
                *(const float4*)&Vh[(size_t)(kv0 + r) * DK + c4];
        }
        __syncthreads();

        float s_[8][4];
        #pragma unroll
        for (int i = 0; i < 8; i++)
            #pragma unroll
            for (int j = 0; j < 4; j++) s_[i][j] = 0.f;

        #pragma unroll 8
        for (int kk = 0; kk < DK; kk++) {
            float a[8], bb[4];
            #pragma unroll
            for (int i = 0; i < 8; i++) a[i] = sQ[(ty * 8 + i) * DK + kk];
            *(float4*)bb = *(const float4*)&sKt[kk * BKV + tx * 4];
            #pragma unroll
            for (int i = 0; i < 8; i++)
                #pragma unroll
                for (int j = 0; j < 4; j++) s_[i][j] += a[i] * bb[j];
        }

        int mv[4];
        #pragma unroll
        for (int j = 0; j < 4; j++) mv[j] = mrow[kv0 + tx * 4 + j];
        #pragma unroll
        for (int i = 0; i < 8; i++)
            #pragma unroll
            for (int j = 0; j < 4; j++)
                s_[i][j] = (mv[j] == 0) ? NEGINF : s_[i][j] * 0.125f;

        #pragma unroll
        for (int i = 0; i < 8; i++) {
            float mx = fmaxf(fmaxf(s_[i][0], s_[i][1]), fmaxf(s_[i][2], s_[i][3]));
            #pragma unroll
            for (int off = 8; off; off >>= 1)
                mx = fmaxf(mx, __shfl_xor_sync(0xffffffffu, mx, off, 16));
            float mn = fmaxf(m_[i], mx);
            float corr = __expf(m_[i] - mn);
            float ls = 0.f;
            #pragma unroll
            for (int j = 0; j < 4; j++) {
                float p = __expf(s_[i][j] - mn);
                sP[(ty * 8 + i) * 65 + tx * 4 + j] = p;
                ls += p;
            }
            #pragma unroll
            for (int off = 8; off; off >>= 1)
                ls += __shfl_xor_sync(0xffffffffu, ls, off, 16);
            l_[i] = l_[i] * corr + ls;
            m_[i] = mn;
            #pragma unroll
            for (int j = 0; j < 4; j++) acc[i][j] *= corr;
        }
        __syncthreads();

        #pragma unroll 8
        for (int kk = 0; kk < BKV; kk++) {
            float a[8], bb[4];
            #pragma unroll
            for (int i = 0; i < 8; i++) a[i] = sP[(ty * 8 + i) * 65 + kk];
            *(float4*)bb = *(const float4*)&sV[kk * DK + tx * 4];
            #pragma unroll
            for (int i = 0; i < 8; i++)
                #pragma unroll
                for (int j = 0; j < 4; j++) acc[i][j] += a[i] * bb[j];
        }
        __syncthreads();
    }

    #pragma unroll
    for (int i = 0; i < 8; i++) {
        float inv = 1.0f / l_[i];
        int row = b * SEQ + q0 + ty * 8 + i;
        float4 v;
        v.x = tf32r(acc[i][0] * inv); v.y = tf32r(acc[i][1] * inv);
        v.z = tf32r(acc[i][2] * inv); v.w = tf32r(acc[i][3] * inv);
        *(float4*)&ctx[(size_t)row * DMODEL + h * DK + tx * 4] = v;
    }
}

// =====================================================================
// launcher
// =====================================================================
extern "C" void kernel_launch(void* const* d_in, const int* in_sizes, int n_in,
                              void* d_out, int out_size)
{
    const float* x    = (const float*)d_in[0];
    const int*   mask = (const int*)  d_in[1];
    const float* wq = (const float*)d_in[2],  *bq = (const float*)d_in[3];
    const float* wk = (const float*)d_in[4],  *bk = (const float*)d_in[5];
    const float* wv = (const float*)d_in[6],  *bv = (const float*)d_in[7];
    const float* wo = (const float*)d_in[8],  *bo = (const float*)d_in[9];
    const float* w1 = (const float*)d_in[10], *b1 = (const float*)d_in[11];
    const float* w2 = (const float*)d_in[12], *b2 = (const float*)d_in[13];
    const float* ln1a = (const float*)d_in[14], *ln1b = (const float*)d_in[15];
    const float* ln2a = (const float*)d_in[16], *ln2b = (const float*)d_in[17];
    float* out = (float*)d_out;

    float *xn, *q, *k, *v, *ctx, *x2, *hbuf;
    float *wqr, *wkr, *wvr, *wor, *w1r, *w2r;
    cudaGetSymbolAddress((void**)&xn,   g_xn);
    cudaGetSymbolAddress((void**)&q,    g_q);
    cudaGetSymbolAddress((void**)&k,    g_k);
    cudaGetSymbolAddress((void**)&v,    g_v);
    cudaGetSymbolAddress((void**)&ctx,  g_ctx);
    cudaGetSymbolAddress((void**)&x2,   g_x2);
    cudaGetSymbolAddress((void**)&hbuf, g_h);
    cudaGetSymbolAddress((void**)&wqr,  g_wqr);
    cudaGetSymbolAddress((void**)&wkr,  g_wkr);
    cudaGetSymbolAddress((void**)&wvr,  g_wvr);
    cudaGetSymbolAddress((void**)&wor,  g_wor);
    cudaGetSymbolAddress((void**)&w1r,  g_w1r);
    cudaGetSymbolAddress((void**)&w2r,  g_w2r);

    cudaFuncSetAttribute(attn_kernel,
                         cudaFuncAttributeMaxDynamicSharedMemorySize,
                         ATTN_SMEM_BYTES);
    cudaFuncSetAttribute(mma_gemm_kernel,
                         cudaFuncAttributeMaxDynamicSharedMemorySize,
                         GEMM_SMEM);

    // tf32-round weights (elementwise copy; layout preserved)
    int n1 = DMODEL * DMODEL / 4, n2 = DMODEL * DFF / 4;
    trunc_kernel<<<(n1 + 255) / 256, 256>>>(wq, wqr, n1);
    trunc_kernel<<<(n1 + 255) / 256, 256>>>(wk, wkr, n1);
    trunc_kernel<<<(n1 + 255) / 256, 256>>>(wv, wvr, n1);
    trunc_kernel<<<(n1 + 255) / 256, 256>>>(wo, wor, n1);
    trunc_kernel<<<(n2 + 255) / 256, 256>>>(w1, w1r, n2);
    trunc_kernel<<<(n2 + 255) / 256, 256>>>(w2, w2r, n2);

    dim3 g768 (DMODEL / BN, MROWS / BM);   // (6, 64)
    dim3 g3072(DFF    / BN, MROWS / BM);   // (24, 64)

    // sublayer 1
    ln_kernel<<<MROWS, 256>>>(x, xn, ln1a, ln1b);
    mma_gemm_kernel<<<g768, 256, GEMM_SMEM>>>(xn, wqr, bq, nullptr, q, MROWS, DMODEL, DMODEL, EPI_QKV);
    mma_gemm_kernel<<<g768, 256, GEMM_SMEM>>>(xn, wkr, bk, nullptr, k, MROWS, DMODEL, DMODEL, EPI_QKV);
    mma_gemm_kernel<<<g768, 256, GEMM_SMEM>>>(xn, wvr, bv, nullptr, v, MROWS, DMODEL, DMODEL, EPI_QKV);
    attn_kernel<<<dim3(SEQ / BQ, BATCH * NHEADS), 256, ATTN_SMEM_BYTES>>>(q, k, v, mask, ctx);
    mma_gemm_kernel<<<g768, 256, GEMM_SMEM>>>(ctx, wor, bo, x, x2, MROWS, DMODEL, DMODEL, EPI_RES);

    // sublayer 2
    ln_kernel<<<MROWS, 256>>>(x2, xn, ln2a, ln2b);
    mma_gemm_kernel<<<g3072, 256, GEMM_SMEM>>>(xn, w1r, b1, nullptr, hbuf, MROWS, DFF, DMODEL, EPI_RELU);
    mma_gemm_kernel<<<g768, 256, GEMM_SMEM>>>(hbuf, w2r, b2, x2, out, MROWS, DMODEL, DFF, EPI_RES);
}

// round 6
// speedup vs baseline: 2.5991x; 1.5817x over previous
#include <cuda_runtime.h>
#include <cuda_pipeline.h>
#include <math.h>
#include <cstdint>

// ---------------- problem constants ----------------
#define BATCH   4
#define SEQ     2048
#define DMODEL  768
#define NHEADS  12
#define DK      64
#define DFF     3072
#define MROWS   (BATCH*SEQ)          // 8192
#define EPS_LN  1e-6f
#define NEGINF  -1.0e9f

// ---------------- scratch (device globals; allocation-free) ----------------
__device__ float g_xn [MROWS*DMODEL];
__device__ float g_q  [MROWS*DMODEL];
__device__ float g_k  [MROWS*DMODEL];
__device__ float g_v  [MROWS*DMODEL];
__device__ float g_ctx[MROWS*DMODEL];
__device__ float g_x2 [MROWS*DMODEL];
__device__ float g_h  [MROWS*DFF];
// tf32-rounded weight copies (same [K,N] layout as inputs)
__device__ float g_wqr[DMODEL*DMODEL];
__device__ float g_wkr[DMODEL*DMODEL];
__device__ float g_wvr[DMODEL*DMODEL];
__device__ float g_wor[DMODEL*DMODEL];
__device__ float g_w1r[DMODEL*DFF];
__device__ float g_w2r[DFF*DMODEL];

// ---------------- helpers ----------------
__device__ __forceinline__ float tf32r(float x) {
    uint32_t y;                                    // tf32 dst must be .b32
    asm("cvt.rna.tf32.f32 %0, %1;" : "=r"(y) : "f"(x));
    return __uint_as_float(y);
}

__device__ __forceinline__ void mma_tf32(float* d,
    uint32_t a0, uint32_t a1, uint32_t a2, uint32_t a3,
    uint32_t b0, uint32_t b1)
{
    asm volatile(
        "mma.sync.aligned.m16n8k8.row.col.f32.tf32.tf32.f32 "
        "{%0,%1,%2,%3}, {%4,%5,%6,%7}, {%8,%9}, {%0,%1,%2,%3};"
        : "+f"(d[0]), "+f"(d[1]), "+f"(d[2]), "+f"(d[3])
        : "r"(a0), "r"(a1), "r"(a2), "r"(a3), "r"(b0), "r"(b1));
}

// =====================================================================
// tf32 truncate-copy for weights
// =====================================================================
__global__ void __launch_bounds__(256) trunc_kernel(
    const float* __restrict__ W, float* __restrict__ Wr, int n4)
{
    int i = blockIdx.x * 256 + threadIdx.x;
    if (i < n4) {
        float4 v = ((const float4*)W)[i];
        v.x = tf32r(v.x); v.y = tf32r(v.y);
        v.z = tf32r(v.z); v.w = tf32r(v.w);
        ((float4*)Wr)[i] = v;
    }
}

// =====================================================================
// LayerNorm (tf32-rounds its output — it feeds GEMM A operands)
// =====================================================================
__device__ __forceinline__ float block_sum_256(float v, float* red) {
    #pragma unroll
    for (int off = 16; off; off >>= 1) v += __shfl_xor_sync(0xffffffffu, v, off);
    int t = threadIdx.x;
    if ((t & 31) == 0) red[t >> 5] = v;
    __syncthreads();
    float s = 0.f;
    #pragma unroll
    for (int w = 0; w < 8; w++) s += red[w];
    __syncthreads();
    return s;
}

__global__ void __launch_bounds__(256) ln_kernel(
    const float* __restrict__ x, float* __restrict__ o,
    const float* __restrict__ ga, const float* __restrict__ gb)
{
    __shared__ float red[8];
    int row = blockIdx.x;
    int t = threadIdx.x;
    const float* xr = x + (size_t)row * DMODEL;
    float v0 = xr[t], v1 = xr[t + 256], v2 = xr[t + 512];
    float mean = block_sum_256(v0 + v1 + v2, red) * (1.0f / 768.0f);
    float d0 = v0 - mean, d1 = v1 - mean, d2 = v2 - mean;
    float ss = block_sum_256(d0*d0 + d1*d1 + d2*d2, red);
    float stdv = sqrtf(ss * (1.0f / 767.0f));      // ddof = 1
    float sc = ga[0] / (EPS_LN + stdv);
    float bb = gb[0];
    float* orow = o + (size_t)row * DMODEL;
    orow[t]       = tf32r(d0 * sc + bb);
    orow[t + 256] = tf32r(d1 * sc + bb);
    orow[t + 512] = tf32r(d2 * sc + bb);
}

// =====================================================================
// tf32 mma.sync GEMM (unchanged from R4, except EPI_QKV rounds output)
// =====================================================================
#define EPI_BIAS 0
#define EPI_RELU 1
#define EPI_RES  2
#define EPI_QKV  3

#define BM 128
#define BN 128
#define BKT 16
#define STG 4
#define APAD 20
#define BPAD 136
#define A_STG (BM*APAD)
#define B_STG (BKT*BPAD)
#define GEMM_SMEM ((STG*(A_STG+B_STG))*4)

__global__ void __launch_bounds__(256) mma_gemm_kernel(
    const float* __restrict__ A, const float* __restrict__ B,
    const float* __restrict__ bias, const float* __restrict__ res,
    float* __restrict__ C, int M, int N, int K, int epi)
{
    extern __shared__ float sm[];
    float* As = sm;
    float* Bs = sm + STG * A_STG;

    int tid = threadIdx.x;
    int wid = tid >> 5, lane = tid & 31;
    int g = lane >> 2, q = lane & 3;
    int wm = (wid >> 2) * 64;
    int wn = (wid & 3) * 32;
    int m0 = blockIdx.y * BM, n0 = blockIdx.x * BN;

    const float* Ab = A + (size_t)m0 * K;
    const float* Bb = B + n0;

    auto load_stage = [&](int st, int k0) {
        float* aS = As + st * A_STG;
        float* bS = Bs + st * B_STG;
        #pragma unroll
        for (int i = 0; i < 8; i++) {
            int e = tid + (i << 8);
            int m = e >> 4, k = e & 15;
            __pipeline_memcpy_async(aS + m * APAD + k,
                                    Ab + (size_t)m * K + k0 + k, 4);
        }
        #pragma unroll
        for (int i = 0; i < 2; i++) {
            int c = tid + (i << 8);
            int k = c >> 5, n4 = (c & 31) << 2;
            __pipeline_memcpy_async(bS + k * BPAD + n4,
                                    Bb + (size_t)(k0 + k) * N + n4, 16);
        }
    };

    float acc[4][4][4];
    #pragma unroll
    for (int mt = 0; mt < 4; mt++)
        #pragma unroll
        for (int nt = 0; nt < 4; nt++)
            #pragma unroll
            for (int c = 0; c < 4; c++) acc[mt][nt][c] = 0.f;

    int nT = K >> 4;
    #pragma unroll
    for (int s = 0; s < STG - 1; s++) {
        load_stage(s, s << 4);
        __pipeline_commit();
    }

    for (int t = 0; t < nT; t++) {
        __pipeline_wait_prior(STG - 2);
        __syncthreads();
        int nx = t + STG - 1;
        if (nx < nT) load_stage(nx & (STG - 1), nx << 4);
        __pipeline_commit();

        int st = t & (STG - 1);
        const float* aS = As + st * A_STG;
        const float* bS = Bs + st * B_STG;

        #pragma unroll
        for (int kk = 0; kk < BKT; kk += 8) {
            uint32_t af[4][4], bf[4][2];
            #pragma unroll
            for (int mt = 0; mt < 4; mt++) {
                const float* ap = aS + (wm + mt * 16 + g) * APAD + kk + q;
                af[mt][0] = __float_as_uint(ap[0]);
                af[mt][1] = __float_as_uint(ap[8 * APAD]);
                af[mt][2] = __float_as_uint(ap[4]);
                af[mt][3] = __float_as_uint(ap[8 * APAD + 4]);
            }
            #pragma unroll
            for (int nt = 0; nt < 4; nt++) {
                const float* bp = bS + (kk + q) * BPAD + wn + nt * 8 + g;
                bf[nt][0] = __float_as_uint(bp[0]);
                bf[nt][1] = __float_as_uint(bp[4 * BPAD]);
            }
            #pragma unroll
            for (int mt = 0; mt < 4; mt++)
                #pragma unroll
                for (int nt = 0; nt < 4; nt++)
                    mma_tf32(acc[mt][nt], af[mt][0], af[mt][1], af[mt][2], af[mt][3],
                             bf[nt][0], bf[nt][1]);
        }
    }

    #pragma unroll
    for (int mt = 0; mt < 4; mt++) {
        #pragma unroll
        for (int half = 0; half < 2; half++) {
            int row = m0 + wm + mt * 16 + g + half * 8;
            #pragma unroll
            for (int nt = 0; nt < 4; nt++) {
                int col = n0 + wn + nt * 8 + 2 * q;
                float c0 = acc[mt][nt][half * 2 + 0];
                float c1 = acc[mt][nt][half * 2 + 1];
                float2 bv = *(const float2*)&bias[col];
                c0 += bv.x; c1 += bv.y;
                if (epi == EPI_RELU) {
                    c0 = tf32r(fmaxf(c0, 0.f));
                    c1 = tf32r(fmaxf(c1, 0.f));
                } else if (epi == EPI_RES) {
                    float2 r2 = *(const float2*)&res[(size_t)row * N + col];
                    c0 += r2.x; c1 += r2.y;
                }
                if (epi == EPI_QKV) {
                    // tf32-round: Q/K/V feed attention tensor ops
                    c0 = tf32r(c0); c1 = tf32r(c1);
                    int b_ = row >> 11, s_ = row & 2047;
                    int h_ = col >> 6,  d_ = col & 63;
                    size_t o = (((size_t)(b_ * NHEADS + h_) * SEQ + s_) << 6) + d_;
                    *(float2*)&C[o] = make_float2(c0, c1);
                } else {
                    *(float2*)&C[(size_t)row * N + col] = make_float2(c0, c1);
                }
            }
        }
    }
}

// =====================================================================
// tf32 mma.sync flash attention.
// 256 thr = 8 warps; warp w owns q-rows [w*16, w*16+16) of a 128-row tile.
// Per kv tile (64): S = Q@K^T via mma (1Mx8N atoms, 8 k-steps),
// warp-local online softmax on fragments, P staged tf32 in smem,
// O += P@V via mma. K/V double-buffered cp.async.
// =====================================================================
#define QS 68
#define KS 68
#define VS 72
#define PS 68
#define NKV 32                      // 2048/64 tiles
#define ATT_SQ   (128*QS)
#define ATT_SK   (64*KS)
#define ATT_SV   (64*VS)
#define ATT_SP   (128*PS)
#define ATTN_SMEM_BYTES ((ATT_SQ + 2*ATT_SK + 2*ATT_SV + ATT_SP)*4 + 2*64*4)

__global__ void __launch_bounds__(256) attn_mma_kernel(
    const float* __restrict__ Q, const float* __restrict__ K,
    const float* __restrict__ V, const int* __restrict__ mask,
    float* __restrict__ ctx)
{
    extern __shared__ float smf[];
    float* sQ = smf;                         // [128][QS]
    float* sK = sQ + ATT_SQ;                 // [2][64][KS]
    float* sV = sK + 2 * ATT_SK;             // [2][64][VS]
    float* sP = sV + 2 * ATT_SV;             // [128][PS]
    int*   sM = (int*)(sP + ATT_SP);         // [2][64]

    int tid = threadIdx.x;
    int wid = tid >> 5, lane = tid & 31;
    int g = lane >> 2, q = lane & 3;
    int bh = blockIdx.y;
    int q0 = blockIdx.x * 128;
    int b  = bh / NHEADS;
    int h  = bh % NHEADS;

    const float* Qh = Q + (size_t)bh * SEQ * DK;
    const float* Kh = K + (size_t)bh * SEQ * DK;
    const float* Vh = V + (size_t)bh * SEQ * DK;
    const int* mrow = mask + b * SEQ;

    // Q tile: 2048 float4 / 256 thr = 8 each
    #pragma unroll
    for (int i = 0; i < 8; i++) {
        int c = tid + 256 * i;
        int r = c >> 4, c4 = (c & 15) << 2;
        *(float4*)&sQ[r * QS + c4] =
            *(const float4*)&Qh[(size_t)(q0 + r) * DK + c4];
    }

    auto loadKV = [&](int buf, int kv0) {
        #pragma unroll
        for (int i = 0; i < 4; i++) {
            int c = tid + 256 * i;
            int r = c >> 4, c4 = (c & 15) << 2;
            __pipeline_memcpy_async(&sK[buf * ATT_SK + r * KS + c4],
                                    &Kh[(size_t)(kv0 + r) * DK + c4], 16);
            __pipeline_memcpy_async(&sV[buf * ATT_SV + r * VS + c4],
                                    &Vh[(size_t)(kv0 + r) * DK + c4], 16);
        }
        if (tid < 64)
            __pipeline_memcpy_async(&sM[buf * 64 + tid], &mrow[kv0 + tid], 4);
    };

    loadKV(0, 0);
    __pipeline_commit();

    float m0 = -1e30f, m1 = -1e30f, l0 = 0.f, l1 = 0.f;
    float oacc[8][4];
    #pragma unroll
    for (int nt = 0; nt < 8; nt++)
        #pragma unroll
        for (int c = 0; c < 4; c++) oacc[nt][c] = 0.f;

    int wr0 = wid * 16;

    for (int t = 0; t < NKV; t++) {
        if (t + 1 < NKV) loadKV((t + 1) & 1, (t + 1) * 64);
        __pipeline_commit();
        __pipeline_wait_prior(1);
        __syncthreads();

        const float* bK = sK + (t & 1) * ATT_SK;
        const float* bV = sV + (t & 1) * ATT_SV;
        const int*   bM = sM + (t & 1) * 64;

        // ---- S = Q @ K^T ----
        float sacc[8][4];
        #pragma unroll
        for (int nt = 0; nt < 8; nt++)
            #pragma unroll
            for (int c = 0; c < 4; c++) sacc[nt][c] = 0.f;

        #pragma unroll
        for (int kk = 0; kk < DK; kk += 8) {
            const float* ap = sQ + (wr0 + g) * QS + kk + q;
            uint32_t a0 = __float_as_uint(ap[0]);
            uint32_t a1 = __float_as_uint(ap[8 * QS]);
            uint32_t a2 = __float_as_uint(ap[4]);
            uint32_t a3 = __float_as_uint(ap[8 * QS + 4]);
            #pragma unroll
            for (int nt = 0; nt < 8; nt++) {
                const float* bp = bK + (nt * 8 + g) * KS + kk + q;
                mma_tf32(sacc[nt], a0, a1, a2, a3,
                         __float_as_uint(bp[0]), __float_as_uint(bp[4]));
            }
        }

        // ---- scale + mask + online softmax (warp-local) ----
        float mx0 = -1e30f, mx1 = -1e30f;
        #pragma unroll
        for (int nt = 0; nt < 8; nt++) {
            int c0i = nt * 8 + 2 * q;
            int mva = bM[c0i], mvb = bM[c0i + 1];
            sacc[nt][0] = mva ? sacc[nt][0] * 0.125f : NEGINF;
            sacc[nt][1] = mvb ? sacc[nt][1] * 0.125f : NEGINF;
            sacc[nt][2] = mva ? sacc[nt][2] * 0.125f : NEGINF;
            sacc[nt][3] = mvb ? sacc[nt][3] * 0.125f : NEGINF;
            mx0 = fmaxf(mx0, fmaxf(sacc[nt][0], sacc[nt][1]));
            mx1 = fmaxf(mx1, fmaxf(sacc[nt][2], sacc[nt][3]));
        }
        #pragma unroll
        for (int off = 1; off < 4; off <<= 1) {
            mx0 = fmaxf(mx0, __shfl_xor_sync(0xffffffffu, mx0, off));
            mx1 = fmaxf(mx1, __shfl_xor_sync(0xffffffffu, mx1, off));
        }
        float mn0 = fmaxf(m0, mx0), mn1 = fmaxf(m1, mx1);
        float cor0 = __expf(m0 - mn0), cor1 = __expf(m1 - mn1);
        float ls0 = 0.f, ls1 = 0.f;
        float* pr0 = sP + (wr0 + g) * PS;
        float* pr1 = pr0 + 8 * PS;
        #pragma unroll
        for (int nt = 0; nt < 8; nt++) {
            int c0i = nt * 8 + 2 * q;
            float p0 = __expf(sacc[nt][0] - mn0);
            float p1 = __expf(sacc[nt][1] - mn0);
            float p2 = __expf(sacc[nt][2] - mn1);
            float p3 = __expf(sacc[nt][3] - mn1);
            ls0 += p0 + p1; ls1 += p2 + p3;
            pr0[c0i]     = tf32r(p0);
            pr0[c0i + 1] = tf32r(p1);
            pr1[c0i]     = tf32r(p2);
            pr1[c0i + 1] = tf32r(p3);
        }
        #pragma unroll
        for (int off = 1; off < 4; off <<= 1) {
            ls0 += __shfl_xor_sync(0xffffffffu, ls0, off);
            ls1 += __shfl_xor_sync(0xffffffffu, ls1, off);
        }
        l0 = l0 * cor0 + ls0; m0 = mn0;
        l1 = l1 * cor1 + ls1; m1 = mn1;
        #pragma unroll
        for (int nt = 0; nt < 8; nt++) {
            oacc[nt][0] *= cor0; oacc[nt][1] *= cor0;
            oacc[nt][2] *= cor1; oacc[nt][3] *= cor1;
        }
        __syncwarp();

        // ---- O += P @ V ----
        #pragma unroll
        for (int kk = 0; kk < 64; kk += 8) {
            const float* ap = sP + (wr0 + g) * PS + kk + q;
            uint32_t a0 = __float_as_uint(ap[0]);
            uint32_t a1 = __float_as_uint(ap[8 * PS]);
            uint32_t a2 = __float_as_uint(ap[4]);
            uint32_t a3 = __float_as_uint(ap[8 * PS + 4]);
            #pragma unroll
            for (int nt = 0; nt < 8; nt++) {
                const float* bp = bV + (kk + q) * VS + nt * 8 + g;
                mma_tf32(oacc[nt], a0, a1, a2, a3,
                         __float_as_uint(bp[0]), __float_as_uint(bp[4 * VS]));
            }
        }
        __syncthreads();   // protect sK/sV buffer reuse next iteration
    }

    // ---- final: divide by l, store ctx [B,S,DMODEL] ----
    float inv0 = 1.0f / l0, inv1 = 1.0f / l1;
    size_t row0 = (size_t)(b * SEQ + q0 + wr0 + g);
    size_t row1 = row0 + 8;
    #pragma unroll
    for (int nt = 0; nt < 8; nt++) {
        int col = h * DK + nt * 8 + 2 * q;
        *(float2*)&ctx[row0 * DMODEL + col] =
            make_float2(tf32r(oacc[nt][0] * inv0), tf32r(oacc[nt][1] * inv0));
        *(float2*)&ctx[row1 * DMODEL + col] =
            make_float2(tf32r(oacc[nt][2] * inv1), tf32r(oacc[nt][3] * inv1));
    }
}

// =====================================================================
// launcher
// =====================================================================
extern "C" void kernel_launch(void* const* d_in, const int* in_sizes, int n_in,
                              void* d_out, int out_size)
{
    const float* x    = (const float*)d_in[0];
    const int*   mask = (const int*)  d_in[1];
    const float* wq = (const float*)d_in[2],  *bq = (const float*)d_in[3];
    const float* wk = (const float*)d_in[4],  *bk = (const float*)d_in[5];
    const float* wv = (const float*)d_in[6],  *bv = (const float*)d_in[7];
    const float* wo = (const float*)d_in[8],  *bo = (const float*)d_in[9];
    const float* w1 = (const float*)d_in[10], *b1 = (const float*)d_in[11];
    const float* w2 = (const float*)d_in[12], *b2 = (const float*)d_in[13];
    const float* ln1a = (const float*)d_in[14], *ln1b = (const float*)d_in[15];
    const float* ln2a = (const float*)d_in[16], *ln2b = (const float*)d_in[17];
    float* out = (float*)d_out;

    float *xn, *q, *k, *v, *ctx, *x2, *hbuf;
    float *wqr, *wkr, *wvr, *wor, *w1r, *w2r;
    cudaGetSymbolAddress((void**)&xn,   g_xn);
    cudaGetSymbolAddress((void**)&q,    g_q);
    cudaGetSymbolAddress((void**)&k,    g_k);
    cudaGetSymbolAddress((void**)&v,    g_v);
    cudaGetSymbolAddress((void**)&ctx,  g_ctx);
    cudaGetSymbolAddress((void**)&x2,   g_x2);
    cudaGetSymbolAddress((void**)&hbuf, g_h);
    cudaGetSymbolAddress((void**)&wqr,  g_wqr);
    cudaGetSymbolAddress((void**)&wkr,  g_wkr);
    cudaGetSymbolAddress((void**)&wvr,  g_wvr);
    cudaGetSymbolAddress((void**)&wor,  g_wor);
    cudaGetSymbolAddress((void**)&w1r,  g_w1r);
    cudaGetSymbolAddress((void**)&w2r,  g_w2r);

    cudaFuncSetAttribute(attn_mma_kernel,
                         cudaFuncAttributeMaxDynamicSharedMemorySize,
                         ATTN_SMEM_BYTES);
    cudaFuncSetAttribute(mma_gemm_kernel,
                         cudaFuncAttributeMaxDynamicSharedMemorySize,
                         GEMM_SMEM);

    int n1 = DMODEL * DMODEL / 4, n2 = DMODEL * DFF / 4;
    trunc_kernel<<<(n1 + 255) / 256, 256>>>(wq, wqr, n1);
    trunc_kernel<<<(n1 + 255) / 256, 256>>>(wk, wkr, n1);
    trunc_kernel<<<(n1 + 255) / 256, 256>>>(wv, wvr, n1);
    trunc_kernel<<<(n1 + 255) / 256, 256>>>(wo, wor, n1);
    trunc_kernel<<<(n2 + 255) / 256, 256>>>(w1, w1r, n2);
    trunc_kernel<<<(n2 + 255) / 256, 256>>>(w2, w2r, n2);

    dim3 g768 (DMODEL / BN, MROWS / BM);
    dim3 g3072(DFF    / BN, MROWS / BM);

    // sublayer 1
    ln_kernel<<<MROWS, 256>>>(x, xn, ln1a, ln1b);
    mma_gemm_kernel<<<g768, 256, GEMM_SMEM>>>(xn, wqr, bq, nullptr, q, MROWS, DMODEL, DMODEL, EPI_QKV);
    mma_gemm_kernel<<<g768, 256, GEMM_SMEM>>>(xn, wkr, bk, nullptr, k, MROWS, DMODEL, DMODEL, EPI_QKV);
    mma_gemm_kernel<<<g768, 256, GEMM_SMEM>>>(xn, wvr, bv, nullptr, v, MROWS, DMODEL, DMODEL, EPI_QKV);
    attn_mma_kernel<<<dim3(SEQ / 128, BATCH * NHEADS), 256, ATTN_SMEM_BYTES>>>(q, k, v, mask, ctx);
    mma_gemm_kernel<<<g768, 256, GEMM_SMEM>>>(ctx, wor, bo, x, x2, MROWS, DMODEL, DMODEL, EPI_RES);

    // sublayer 2
    ln_kernel<<<MROWS, 256>>>(x2, xn, ln2a, ln2b);
    mma_gemm_kernel<<<g3072, 256, GEMM_SMEM>>>(xn, w1r, b1, nullptr, hbuf, MROWS, DFF, DMODEL, EPI_RELU);
    mma_gemm_kernel<<<g768, 256, GEMM_SMEM>>>(hbuf, w2r, b2, x2, out, MROWS, DMODEL, DFF, EPI_RES);
}

// round 7
// speedup vs baseline: 3.1582x; 1.2151x over previous
#include <cuda_runtime.h>
#include <cuda_pipeline.h>
#include <math.h>
#include <cstdint>

// ---------------- problem constants ----------------
#define BATCH   4
#define SEQ     2048
#define DMODEL  768
#define NHEADS  12
#define DK      64
#define DFF     3072
#define MROWS   (BATCH*SEQ)          // 8192
#define EPS_LN  1e-6f
#define NEGINF  -1.0e9f

// ---------------- scratch (device globals; allocation-free) ----------------
__device__ float g_xn [MROWS*DMODEL];
__device__ float g_q  [MROWS*DMODEL];
__device__ float g_k  [MROWS*DMODEL];
__device__ float g_v  [MROWS*DMODEL];
__device__ float g_ctx[MROWS*DMODEL];
__device__ float g_x2 [MROWS*DMODEL];
__device__ float g_h  [MROWS*DFF];
// tf32-rounded weight copies (same [K,N] layout as inputs)
__device__ float g_wqr[DMODEL*DMODEL];
__device__ float g_wkr[DMODEL*DMODEL];
__device__ float g_wvr[DMODEL*DMODEL];
__device__ float g_wor[DMODEL*DMODEL];
__device__ float g_w1r[DMODEL*DFF];
__device__ float g_w2r[DFF*DMODEL];

// ---------------- helpers ----------------
__device__ __forceinline__ float tf32r(float x) {
    uint32_t y;                                    // tf32 dst must be .b32
    asm("cvt.rna.tf32.f32 %0, %1;" : "=r"(y) : "f"(x));
    return __uint_as_float(y);
}

__device__ __forceinline__ void mma_tf32(float* d,
    uint32_t a0, uint32_t a1, uint32_t a2, uint32_t a3,
    uint32_t b0, uint32_t b1)
{
    asm volatile(
        "mma.sync.aligned.m16n8k8.row.col.f32.tf32.tf32.f32 "
        "{%0,%1,%2,%3}, {%4,%5,%6,%7}, {%8,%9}, {%0,%1,%2,%3};"
        : "+f"(d[0]), "+f"(d[1]), "+f"(d[2]), "+f"(d[3])
        : "r"(a0), "r"(a1), "r"(a2), "r"(a3), "r"(b0), "r"(b1));
}

// =====================================================================
// tf32 truncate-copy for weights
// =====================================================================
__global__ void __launch_bounds__(256) trunc_kernel(
    const float* __restrict__ W, float* __restrict__ Wr, int n4)
{
    int i = blockIdx.x * 256 + threadIdx.x;
    if (i < n4) {
        float4 v = ((const float4*)W)[i];
        v.x = tf32r(v.x); v.y = tf32r(v.y);
        v.z = tf32r(v.z); v.w = tf32r(v.w);
        ((float4*)Wr)[i] = v;
    }
}

// =====================================================================
// LayerNorm (tf32-rounds its output — it feeds GEMM A operands)
// =====================================================================
__device__ __forceinline__ float block_sum_256(float v, float* red) {
    #pragma unroll
    for (int off = 16; off; off >>= 1) v += __shfl_xor_sync(0xffffffffu, v, off);
    int t = threadIdx.x;
    if ((t & 31) == 0) red[t >> 5] = v;
    __syncthreads();
    float s = 0.f;
    #pragma unroll
    for (int w = 0; w < 8; w++) s += red[w];
    __syncthreads();
    return s;
}

__global__ void __launch_bounds__(256) ln_kernel(
    const float* __restrict__ x, float* __restrict__ o,
    const float* __restrict__ ga, const float* __restrict__ gb)
{
    __shared__ float red[8];
    int row = blockIdx.x;
    int t = threadIdx.x;
    const float* xr = x + (size_t)row * DMODEL;
    float v0 = xr[t], v1 = xr[t + 256], v2 = xr[t + 512];
    float mean = block_sum_256(v0 + v1 + v2, red) * (1.0f / 768.0f);
    float d0 = v0 - mean, d1 = v1 - mean, d2 = v2 - mean;
    float ss = block_sum_256(d0*d0 + d1*d1 + d2*d2, red);
    float stdv = sqrtf(ss * (1.0f / 767.0f));      // ddof = 1
    float sc = ga[0] / (EPS_LN + stdv);
    float bb = gb[0];
    float* orow = o + (size_t)row * DMODEL;
    orow[t]       = tf32r(d0 * sc + bb);
    orow[t + 256] = tf32r(d1 * sc + bb);
    orow[t + 512] = tf32r(d2 * sc + bb);
}

// =====================================================================
// tf32 mma.sync GEMM v2: CTA 128x128, 4 warps, warp tile 64x64,
// BK=16, 4-stage cp.async, all-float4 global loads.
// Per warp-kstep: 32 LDS / 32 MMA (was 24/16) — issue-bound fix.
// =====================================================================
#define EPI_BIAS 0
#define EPI_RELU 1
#define EPI_RES  2
#define EPI_QKV  3

#define BM 128
#define BN 128
#define BKT 16
#define STG 4
#define APAD 20
#define BPAD 136
#define A_STG (BM*APAD)                 // 2560 floats
#define B_STG (BKT*BPAD)                // 2176 floats
#define GEMM_SMEM ((STG*(A_STG+B_STG))*4)   // 75776 B

__global__ void __launch_bounds__(128) mma_gemm_kernel(
    const float* __restrict__ A, const float* __restrict__ B,
    const float* __restrict__ bias, const float* __restrict__ res,
    float* __restrict__ C, int M, int N, int K, int epi)
{
    extern __shared__ float sm[];
    float* As = sm;                     // [STG][BM][APAD]
    float* Bs = sm + STG * A_STG;       // [STG][BKT][BPAD]

    int tid = threadIdx.x;
    int wid = tid >> 5, lane = tid & 31;
    int g = lane >> 2, q = lane & 3;
    int wm = (wid >> 1) * 64;           // warp M offset (0/64)
    int wn = (wid & 1) * 64;            // warp N offset (0/64)
    int m0 = blockIdx.y * BM, n0 = blockIdx.x * BN;

    const float* Ab = A + (size_t)m0 * K;
    const float* Bb = B + n0;

    // per stage: A = 512 float4 chunks, B = 512 float4 chunks; 128 thr -> 4+4
    auto load_stage = [&](int st, int k0) {
        float* aS = As + st * A_STG;
        float* bS = Bs + st * B_STG;
        #pragma unroll
        for (int i = 0; i < 4; i++) {
            int c = tid + (i << 7);
            int m = c >> 2, k4 = (c & 3) << 2;
            __pipeline_memcpy_async(aS + m * APAD + k4,
                                    Ab + (size_t)m * K + k0 + k4, 16);
        }
        #pragma unroll
        for (int i = 0; i < 4; i++) {
            int c = tid + (i << 7);
            int k = c >> 5, n4 = (c & 31) << 2;
            __pipeline_memcpy_async(bS + k * BPAD + n4,
                                    Bb + (size_t)(k0 + k) * N + n4, 16);
        }
    };

    float acc[4][8][4];
    #pragma unroll
    for (int mt = 0; mt < 4; mt++)
        #pragma unroll
        for (int nt = 0; nt < 8; nt++)
            #pragma unroll
            for (int c = 0; c < 4; c++) acc[mt][nt][c] = 0.f;

    int nT = K >> 4;
    #pragma unroll
    for (int s = 0; s < STG - 1; s++) {
        load_stage(s, s << 4);
        __pipeline_commit();
    }

    for (int t = 0; t < nT; t++) {
        __pipeline_wait_prior(STG - 2);
        __syncthreads();
        int nx = t + STG - 1;
        if (nx < nT) load_stage(nx & (STG - 1), nx << 4);
        __pipeline_commit();

        int st = t & (STG - 1);
        const float* aS = As + st * A_STG;
        const float* bS = Bs + st * B_STG;

        #pragma unroll
        for (int kk = 0; kk < BKT; kk += 8) {
            uint32_t af[4][4], bf[8][2];
            #pragma unroll
            for (int mt = 0; mt < 4; mt++) {
                const float* ap = aS + (wm + mt * 16 + g) * APAD + kk + q;
                af[mt][0] = __float_as_uint(ap[0]);
                af[mt][1] = __float_as_uint(ap[8 * APAD]);
                af[mt][2] = __float_as_uint(ap[4]);
                af[mt][3] = __float_as_uint(ap[8 * APAD + 4]);
            }
            #pragma unroll
            for (int nt = 0; nt < 8; nt++) {
                const float* bp = bS + (kk + q) * BPAD + wn + nt * 8 + g;
                bf[nt][0] = __float_as_uint(bp[0]);
                bf[nt][1] = __float_as_uint(bp[4 * BPAD]);
            }
            #pragma unroll
            for (int mt = 0; mt < 4; mt++)
                #pragma unroll
                for (int nt = 0; nt < 8; nt++)
                    mma_tf32(acc[mt][nt], af[mt][0], af[mt][1], af[mt][2], af[mt][3],
                             bf[nt][0], bf[nt][1]);
        }
    }

    // ----- epilogue -----
    #pragma unroll
    for (int mt = 0; mt < 4; mt++) {
        #pragma unroll
        for (int half = 0; half < 2; half++) {
            int row = m0 + wm + mt * 16 + g + half * 8;
            #pragma unroll
            for (int nt = 0; nt < 8; nt++) {
                int col = n0 + wn + nt * 8 + 2 * q;
                float c0 = acc[mt][nt][half * 2 + 0];
                float c1 = acc[mt][nt][half * 2 + 1];
                float2 bv = *(const float2*)&bias[col];
                c0 += bv.x; c1 += bv.y;
                if (epi == EPI_RELU) {
                    c0 = tf32r(fmaxf(c0, 0.f));
                    c1 = tf32r(fmaxf(c1, 0.f));
                } else if (epi == EPI_RES) {
                    float2 r2 = *(const float2*)&res[(size_t)row * N + col];
                    c0 += r2.x; c1 += r2.y;
                }
                if (epi == EPI_QKV) {
                    c0 = tf32r(c0); c1 = tf32r(c1);
                    int b_ = row >> 11, s_ = row & 2047;
                    int h_ = col >> 6,  d_ = col & 63;
                    size_t o = (((size_t)(b_ * NHEADS + h_) * SEQ + s_) << 6) + d_;
                    *(float2*)&C[o] = make_float2(c0, c1);
                } else {
                    *(float2*)&C[(size_t)row * N + col] = make_float2(c0, c1);
                }
            }
        }
    }
}

// =====================================================================
// tf32 mma.sync flash attention (unchanged from R6 WIN)
// =====================================================================
#define QS 68
#define KS 68
#define VS 72
#define PS 68
#define NKV 32
#define ATT_SQ   (128*QS)
#define ATT_SK   (64*KS)
#define ATT_SV   (64*VS)
#define ATT_SP   (128*PS)
#define ATTN_SMEM_BYTES ((ATT_SQ + 2*ATT_SK + 2*ATT_SV + ATT_SP)*4 + 2*64*4)

__global__ void __launch_bounds__(256) attn_mma_kernel(
    const float* __restrict__ Q, const float* __restrict__ K,
    const float* __restrict__ V, const int* __restrict__ mask,
    float* __restrict__ ctx)
{
    extern __shared__ float smf[];
    float* sQ = smf;                         // [128][QS]
    float* sK = sQ + ATT_SQ;                 // [2][64][KS]
    float* sV = sK + 2 * ATT_SK;             // [2][64][VS]
    float* sP = sV + 2 * ATT_SV;             // [128][PS]
    int*   sM = (int*)(sP + ATT_SP);         // [2][64]

    int tid = threadIdx.x;
    int wid = tid >> 5, lane = tid & 31;
    int g = lane >> 2, q = lane & 3;
    int bh = blockIdx.y;
    int q0 = blockIdx.x * 128;
    int b  = bh / NHEADS;
    int h  = bh % NHEADS;

    const float* Qh = Q + (size_t)bh * SEQ * DK;
    const float* Kh = K + (size_t)bh * SEQ * DK;
    const float* Vh = V + (size_t)bh * SEQ * DK;
    const int* mrow = mask + b * SEQ;

    #pragma unroll
    for (int i = 0; i < 8; i++) {
        int c = tid + 256 * i;
        int r = c >> 4, c4 = (c & 15) << 2;
        *(float4*)&sQ[r * QS + c4] =
            *(const float4*)&Qh[(size_t)(q0 + r) * DK + c4];
    }

    auto loadKV = [&](int buf, int kv0) {
        #pragma unroll
        for (int i = 0; i < 4; i++) {
            int c = tid + 256 * i;
            int r = c >> 4, c4 = (c & 15) << 2;
            __pipeline_memcpy_async(&sK[buf * ATT_SK + r * KS + c4],
                                    &Kh[(size_t)(kv0 + r) * DK + c4], 16);
            __pipeline_memcpy_async(&sV[buf * ATT_SV + r * VS + c4],
                                    &Vh[(size_t)(kv0 + r) * DK + c4], 16);
        }
        if (tid < 64)
            __pipeline_memcpy_async(&sM[buf * 64 + tid], &mrow[kv0 + tid], 4);
    };

    loadKV(0, 0);
    __pipeline_commit();

    float m0 = -1e30f, m1 = -1e30f, l0 = 0.f, l1 = 0.f;
    float oacc[8][4];
    #pragma unroll
    for (int nt = 0; nt < 8; nt++)
        #pragma unroll
        for (int c = 0; c < 4; c++) oacc[nt][c] = 0.f;

    int wr0 = wid * 16;

    for (int t = 0; t < NKV; t++) {
        if (t + 1 < NKV) loadKV((t + 1) & 1, (t + 1) * 64);
        __pipeline_commit();
        __pipeline_wait_prior(1);
        __syncthreads();

        const float* bK = sK + (t & 1) * ATT_SK;
        const float* bV = sV + (t & 1) * ATT_SV;
        const int*   bM = sM + (t & 1) * 64;

        float sacc[8][4];
        #pragma unroll
        for (int nt = 0; nt < 8; nt++)
            #pragma unroll
            for (int c = 0; c < 4; c++) sacc[nt][c] = 0.f;

        #pragma unroll
        for (int kk = 0; kk < DK; kk += 8) {
            const float* ap = sQ + (wr0 + g) * QS + kk + q;
            uint32_t a0 = __float_as_uint(ap[0]);
            uint32_t a1 = __float_as_uint(ap[8 * QS]);
            uint32_t a2 = __float_as_uint(ap[4]);
            uint32_t a3 = __float_as_uint(ap[8 * QS + 4]);
            #pragma unroll
            for (int nt = 0; nt < 8; nt++) {
                const float* bp = bK + (nt * 8 + g) * KS + kk + q;
                mma_tf32(sacc[nt], a0, a1, a2, a3,
                         __float_as_uint(bp[0]), __float_as_uint(bp[4]));
            }
        }

        float mx0 = -1e30f, mx1 = -1e30f;
        #pragma unroll
        for (int nt = 0; nt < 8; nt++) {
            int c0i = nt * 8 + 2 * q;
            int mva = bM[c0i], mvb = bM[c0i + 1];
            sacc[nt][0] = mva ? sacc[nt][0] * 0.125f : NEGINF;
            sacc[nt][1] = mvb ? sacc[nt][1] * 0.125f : NEGINF;
            sacc[nt][2] = mva ? sacc[nt][2] * 0.125f : NEGINF;
            sacc[nt][3] = mvb ? sacc[nt][3] * 0.125f : NEGINF;
            mx0 = fmaxf(mx0, fmaxf(sacc[nt][0], sacc[nt][1]));
            mx1 = fmaxf(mx1, fmaxf(sacc[nt][2], sacc[nt][3]));
        }
        #pragma unroll
        for (int off = 1; off < 4; off <<= 1) {
            mx0 = fmaxf(mx0, __shfl_xor_sync(0xffffffffu, mx0, off));
            mx1 = fmaxf(mx1, __shfl_xor_sync(0xffffffffu, mx1, off));
        }
        float mn0 = fmaxf(m0, mx0), mn1 = fmaxf(m1, mx1);
        float cor0 = __expf(m0 - mn0), cor1 = __expf(m1 - mn1);
        float ls0 = 0.f, ls1 = 0.f;
        float* pr0 = sP + (wr0 + g) * PS;
        float* pr1 = pr0 + 8 * PS;
        #pragma unroll
        for (int nt = 0; nt < 8; nt++) {
            int c0i = nt * 8 + 2 * q;
            float p0 = __expf(sacc[nt][0] - mn0);
            float p1 = __expf(sacc[nt][1] - mn0);
            float p2 = __expf(sacc[nt][2] - mn1);
            float p3 = __expf(sacc[nt][3] - mn1);
            ls0 += p0 + p1; ls1 += p2 + p3;
            pr0[c0i]     = tf32r(p0);
            pr0[c0i + 1] = tf32r(p1);
            pr1[c0i]     = tf32r(p2);
            pr1[c0i + 1] = tf32r(p3);
        }
        #pragma unroll
        for (int off = 1; off < 4; off <<= 1) {
            ls0 += __shfl_xor_sync(0xffffffffu, ls0, off);
            ls1 += __shfl_xor_sync(0xffffffffu, ls1, off);
        }
        l0 = l0 * cor0 + ls0; m0 = mn0;
        l1 = l1 * cor1 + ls1; m1 = mn1;
        #pragma unroll
        for (int nt = 0; nt < 8; nt++) {
            oacc[nt][0] *= cor0; oacc[nt][1] *= cor0;
            oacc[nt][2] *= cor1; oacc[nt][3] *= cor1;
        }
        __syncwarp();

        #pragma unroll
        for (int kk = 0; kk < 64; kk += 8) {
            const float* ap = sP + (wr0 + g) * PS + kk + q;
            uint32_t a0 = __float_as_uint(ap[0]);
            uint32_t a1 = __float_as_uint(ap[8 * PS]);
            uint32_t a2 = __float_as_uint(ap[4]);
            uint32_t a3 = __float_as_uint(ap[8 * PS + 4]);
            #pragma unroll
            for (int nt = 0; nt < 8; nt++) {
                const float* bp = bV + (kk + q) * VS + nt * 8 + g;
                mma_tf32(oacc[nt], a0, a1, a2, a3,
                         __float_as_uint(bp[0]), __float_as_uint(bp[4 * VS]));
            }
        }
        __syncthreads();
    }

    float inv0 = 1.0f / l0, inv1 = 1.0f / l1;
    size_t row0 = (size_t)(b * SEQ + q0 + wr0 + g);
    size_t row1 = row0 + 8;
    #pragma unroll
    for (int nt = 0; nt < 8; nt++) {
        int col = h * DK + nt * 8 + 2 * q;
        *(float2*)&ctx[row0 * DMODEL + col] =
            make_float2(tf32r(oacc[nt][0] * inv0), tf32r(oacc[nt][1] * inv0));
        *(float2*)&ctx[row1 * DMODEL + col] =
            make_float2(tf32r(oacc[nt][2] * inv1), tf32r(oacc[nt][3] * inv1));
    }
}

// =====================================================================
// launcher
// =====================================================================
extern "C" void kernel_launch(void* const* d_in, const int* in_sizes, int n_in,
                              void* d_out, int out_size)
{
    const float* x    = (const float*)d_in[0];
    const int*   mask = (const int*)  d_in[1];
    const float* wq = (const float*)d_in[2],  *bq = (const float*)d_in[3];
    const float* wk = (const float*)d_in[4],  *bk = (const float*)d_in[5];
    const float* wv = (const float*)d_in[6],  *bv = (const float*)d_in[7];
    const float* wo = (const float*)d_in[8],  *bo = (const float*)d_in[9];
    const float* w1 = (const float*)d_in[10], *b1 = (const float*)d_in[11];
    const float* w2 = (const float*)d_in[12], *b2 = (const float*)d_in[13];
    const float* ln1a = (const float*)d_in[14], *ln1b = (const float*)d_in[15];
    const float* ln2a = (const float*)d_in[16], *ln2b = (const float*)d_in[17];
    float* out = (float*)d_out;

    float *xn, *q, *k, *v, *ctx, *x2, *hbuf;
    float *wqr, *wkr, *wvr, *wor, *w1r, *w2r;
    cudaGetSymbolAddress((void**)&xn,   g_xn);
    cudaGetSymbolAddress((void**)&q,    g_q);
    cudaGetSymbolAddress((void**)&k,    g_k);
    cudaGetSymbolAddress((void**)&v,    g_v);
    cudaGetSymbolAddress((void**)&ctx,  g_ctx);
    cudaGetSymbolAddress((void**)&x2,   g_x2);
    cudaGetSymbolAddress((void**)&hbuf, g_h);
    cudaGetSymbolAddress((void**)&wqr,  g_wqr);
    cudaGetSymbolAddress((void**)&wkr,  g_wkr);
    cudaGetSymbolAddress((void**)&wvr,  g_wvr);
    cudaGetSymbolAddress((void**)&wor,  g_wor);
    cudaGetSymbolAddress((void**)&w1r,  g_w1r);
    cudaGetSymbolAddress((void**)&w2r,  g_w2r);

    cudaFuncSetAttribute(attn_mma_kernel,
                         cudaFuncAttributeMaxDynamicSharedMemorySize,
                         ATTN_SMEM_BYTES);
    cudaFuncSetAttribute(mma_gemm_kernel,
                         cudaFuncAttributeMaxDynamicSharedMemorySize,
                         GEMM_SMEM);

    int n1 = DMODEL * DMODEL / 4, n2 = DMODEL * DFF / 4;
    trunc_kernel<<<(n1 + 255) / 256, 256>>>(wq, wqr, n1);
    trunc_kernel<<<(n1 + 255) / 256, 256>>>(wk, wkr, n1);
    trunc_kernel<<<(n1 + 255) / 256, 256>>>(wv, wvr, n1);
    trunc_kernel<<<(n1 + 255) / 256, 256>>>(wo, wor, n1);
    trunc_kernel<<<(n2 + 255) / 256, 256>>>(w1, w1r, n2);
    trunc_kernel<<<(n2 + 255) / 256, 256>>>(w2, w2r, n2);

    dim3 g768 (DMODEL / BN, MROWS / BM);   // (6, 64)
    dim3 g3072(DFF    / BN, MROWS / BM);   // (24, 64)

    // sublayer 1
    ln_kernel<<<MROWS, 256>>>(x, xn, ln1a, ln1b);
    mma_gemm_kernel<<<g768, 128, GEMM_SMEM>>>(xn, wqr, bq, nullptr, q, MROWS, DMODEL, DMODEL, EPI_QKV);
    mma_gemm_kernel<<<g768, 128, GEMM_SMEM>>>(xn, wkr, bk, nullptr, k, MROWS, DMODEL, DMODEL, EPI_QKV);
    mma_gemm_kernel<<<g768, 128, GEMM_SMEM>>>(xn, wvr, bv, nullptr, v, MROWS, DMODEL, DMODEL, EPI_QKV);
    attn_mma_kernel<<<dim3(SEQ / 128, BATCH * NHEADS), 256, ATTN_SMEM_BYTES>>>(q, k, v, mask, ctx);
    mma_gemm_kernel<<<g768, 128, GEMM_SMEM>>>(ctx, wor, bo, x, x2, MROWS, DMODEL, DMODEL, EPI_RES);

    // sublayer 2
    ln_kernel<<<MROWS, 256>>>(x2, xn, ln2a, ln2b);
    mma_gemm_kernel<<<g3072, 128, GEMM_SMEM>>>(xn, w1r, b1, nullptr, hbuf, MROWS, DFF, DMODEL, EPI_RELU);
    mma_gemm_kernel<<<g768, 128, GEMM_SMEM>>>(hbuf, w2r, b2, x2, out, MROWS, DMODEL, DFF, EPI_RES);
}

// round 8
// speedup vs baseline: 3.4074x; 1.0789x over previous
#include <cuda_runtime.h>
#include <cuda_pipeline.h>
#include <math.h>
#include <cstdint>

// ---------------- problem constants ----------------
#define BATCH   4
#define SEQ     2048
#define DMODEL  768
#define NHEADS  12
#define DK      64
#define DFF     3072
#define MROWS   (BATCH*SEQ)          // 8192
#define EPS_LN  1e-6f
#define NEGINF  -1.0e9f

// ---------------- scratch (device globals; allocation-free) ----------------
__device__ float g_xn  [MROWS*DMODEL];
__device__ float g_qkv [3*MROWS*DMODEL];     // [q|k|v], each [B*H, S, 64]
__device__ float g_ctx [MROWS*DMODEL];
__device__ float g_x2  [MROWS*DMODEL];
__device__ float g_h   [MROWS*DFF];
// tf32-rounded weights
__device__ float g_wqkv[DMODEL*3*DMODEL];    // [768][2304] = [wq|wk|wv]
__device__ float g_w1r [DMODEL*DFF];
__device__ float g_w2r [DFF*DMODEL];
__device__ float g_wor [DMODEL*DMODEL];

// ---------------- helpers ----------------
__device__ __forceinline__ float tf32r(float x) {
    uint32_t y;
    asm("cvt.rna.tf32.f32 %0, %1;" : "=r"(y) : "f"(x));
    return __uint_as_float(y);
}

__device__ __forceinline__ void mma_tf32(float* d,
    uint32_t a0, uint32_t a1, uint32_t a2, uint32_t a3,
    uint32_t b0, uint32_t b1)
{
    asm volatile(
        "mma.sync.aligned.m16n8k8.row.col.f32.tf32.tf32.f32 "
        "{%0,%1,%2,%3}, {%4,%5,%6,%7}, {%8,%9}, {%0,%1,%2,%3};"
        : "+f"(d[0]), "+f"(d[1]), "+f"(d[2]), "+f"(d[3])
        : "r"(a0), "r"(a1), "r"(a2), "r"(a3), "r"(b0), "r"(b1));
}

// =====================================================================
// trunc kernels
// =====================================================================
__global__ void __launch_bounds__(256) trunc_kernel(
    const float* __restrict__ W, float* __restrict__ Wr, int n4)
{
    int i = blockIdx.x * 256 + threadIdx.x;
    if (i < n4) {
        float4 v = ((const float4*)W)[i];
        v.x = tf32r(v.x); v.y = tf32r(v.y);
        v.z = tf32r(v.z); v.w = tf32r(v.w);
        ((float4*)Wr)[i] = v;
    }
}

// concat wq|wk|wv -> [768][2304], tf32-rounded
__global__ void __launch_bounds__(256) trunc_qkv_kernel(
    const float* __restrict__ wq, const float* __restrict__ wk,
    const float* __restrict__ wv, float* __restrict__ out)
{
    int i = blockIdx.x * 256 + threadIdx.x;      // float4 idx in [0, 768*768/4)
    if (i >= DMODEL * DMODEL / 4) return;
    int k = i / (DMODEL / 4);
    int c = (i % (DMODEL / 4)) * 4;
    const float* srcs[3] = {wq, wk, wv};
    #pragma unroll
    for (int t = 0; t < 3; t++) {
        float4 v = *(const float4*)&srcs[t][(size_t)k * DMODEL + c];
        v.x = tf32r(v.x); v.y = tf32r(v.y);
        v.z = tf32r(v.z); v.w = tf32r(v.w);
        *(float4*)&out[(size_t)k * (3 * DMODEL) + t * DMODEL + c] = v;
    }
}

// =====================================================================
// LayerNorm: warp-per-row, 8 rows/block, shuffle-only reductions
// =====================================================================
__global__ void __launch_bounds__(256) ln_kernel(
    const float* __restrict__ x, float* __restrict__ o,
    const float* __restrict__ ga, const float* __restrict__ gb)
{
    int wid = threadIdx.x >> 5, lane = threadIdx.x & 31;
    size_t row = (size_t)blockIdx.x * 8 + wid;
    const float4* xr = (const float4*)(x + row * DMODEL);
    float4 v[6];
    float s = 0.f;
    #pragma unroll
    for (int j = 0; j < 6; j++) {
        v[j] = xr[lane + 32 * j];
        s += v[j].x + v[j].y + v[j].z + v[j].w;
    }
    #pragma unroll
    for (int off = 16; off; off >>= 1) s += __shfl_xor_sync(0xffffffffu, s, off);
    float mean = s * (1.0f / 768.0f);
    float ss = 0.f;
    #pragma unroll
    for (int j = 0; j < 6; j++) {
        v[j].x -= mean; v[j].y -= mean; v[j].z -= mean; v[j].w -= mean;
        ss += v[j].x * v[j].x + v[j].y * v[j].y + v[j].z * v[j].z + v[j].w * v[j].w;
    }
    #pragma unroll
    for (int off = 16; off; off >>= 1) ss += __shfl_xor_sync(0xffffffffu, ss, off);
    float stdv = sqrtf(ss * (1.0f / 767.0f));          // ddof = 1
    float sc = ga[0] / (EPS_LN + stdv);
    float bb = gb[0];
    float4* orow = (float4*)(o + row * DMODEL);
    #pragma unroll
    for (int j = 0; j < 6; j++) {
        float4 w;
        w.x = tf32r(v[j].x * sc + bb);
        w.y = tf32r(v[j].y * sc + bb);
        w.z = tf32r(v[j].z * sc + bb);
        w.w = tf32r(v[j].w * sc + bb);
        orow[lane + 32 * j] = w;
    }
}

// =====================================================================
// tf32 mma.sync GEMM (R7 mainloop; EPI_QKV3 = fused q/k/v epilogue)
// =====================================================================
#define EPI_BIAS 0
#define EPI_RELU 1
#define EPI_RES  2
#define EPI_QKV3 3

#define BM 128
#define BN 128
#define BKT 16
#define STG 4
#define APAD 20
#define BPAD 136
#define A_STG (BM*APAD)
#define B_STG (BKT*BPAD)
#define GEMM_SMEM ((STG*(A_STG+B_STG))*4)

__global__ void __launch_bounds__(128) mma_gemm_kernel(
    const float* __restrict__ A, const float* __restrict__ B,
    const float* __restrict__ bias, const float* __restrict__ bias2,
    const float* __restrict__ bias3, const float* __restrict__ res,
    float* __restrict__ C, int M, int N, int K, int epi)
{
    extern __shared__ float sm[];
    float* As = sm;
    float* Bs = sm + STG * A_STG;

    int tid = threadIdx.x;
    int wid = tid >> 5, lane = tid & 31;
    int g = lane >> 2, q = lane & 3;
    int wm = (wid >> 1) * 64;
    int wn = (wid & 1) * 64;
    int m0 = blockIdx.y * BM, n0 = blockIdx.x * BN;

    const float* Ab = A + (size_t)m0 * K;
    const float* Bb = B + n0;

    auto load_stage = [&](int st, int k0) {
        float* aS = As + st * A_STG;
        float* bS = Bs + st * B_STG;
        #pragma unroll
        for (int i = 0; i < 4; i++) {
            int c = tid + (i << 7);
            int m = c >> 2, k4 = (c & 3) << 2;
            __pipeline_memcpy_async(aS + m * APAD + k4,
                                    Ab + (size_t)m * K + k0 + k4, 16);
        }
        #pragma unroll
        for (int i = 0; i < 4; i++) {
            int c = tid + (i << 7);
            int k = c >> 5, n4 = (c & 31) << 2;
            __pipeline_memcpy_async(bS + k * BPAD + n4,
                                    Bb + (size_t)(k0 + k) * N + n4, 16);
        }
    };

    float acc[4][8][4];
    #pragma unroll
    for (int mt = 0; mt < 4; mt++)
        #pragma unroll
        for (int nt = 0; nt < 8; nt++)
            #pragma unroll
            for (int c = 0; c < 4; c++) acc[mt][nt][c] = 0.f;

    int nT = K >> 4;
    #pragma unroll
    for (int s = 0; s < STG - 1; s++) {
        load_stage(s, s << 4);
        __pipeline_commit();
    }

    for (int t = 0; t < nT; t++) {
        __pipeline_wait_prior(STG - 2);
        __syncthreads();
        int nx = t + STG - 1;
        if (nx < nT) load_stage(nx & (STG - 1), nx << 4);
        __pipeline_commit();

        int st = t & (STG - 1);
        const float* aS = As + st * A_STG;
        const float* bS = Bs + st * B_STG;

        #pragma unroll
        for (int kk = 0; kk < BKT; kk += 8) {
            uint32_t af[4][4], bf[8][2];
            #pragma unroll
            for (int mt = 0; mt < 4; mt++) {
                const float* ap = aS + (wm + mt * 16 + g) * APAD + kk + q;
                af[mt][0] = __float_as_uint(ap[0]);
                af[mt][1] = __float_as_uint(ap[8 * APAD]);
                af[mt][2] = __float_as_uint(ap[4]);
                af[mt][3] = __float_as_uint(ap[8 * APAD + 4]);
            }
            #pragma unroll
            for (int nt = 0; nt < 8; nt++) {
                const float* bp = bS + (kk + q) * BPAD + wn + nt * 8 + g;
                bf[nt][0] = __float_as_uint(bp[0]);
                bf[nt][1] = __float_as_uint(bp[4 * BPAD]);
            }
            #pragma unroll
            for (int mt = 0; mt < 4; mt++)
                #pragma unroll
                for (int nt = 0; nt < 8; nt++)
                    mma_tf32(acc[mt][nt], af[mt][0], af[mt][1], af[mt][2], af[mt][3],
                             bf[nt][0], bf[nt][1]);
        }
    }

    // ----- epilogue -----
    #pragma unroll
    for (int mt = 0; mt < 4; mt++) {
        #pragma unroll
        for (int half = 0; half < 2; half++) {
            int row = m0 + wm + mt * 16 + g + half * 8;
            #pragma unroll
            for (int nt = 0; nt < 8; nt++) {
                int col = n0 + wn + nt * 8 + 2 * q;
                float c0 = acc[mt][nt][half * 2 + 0];
                float c1 = acc[mt][nt][half * 2 + 1];
                if (epi == EPI_QKV3) {
                    int t_ = col / DMODEL;            // 0=q 1=k 2=v
                    int within = col - t_ * DMODEL;
                    const float* bptr = (t_ == 0) ? bias : (t_ == 1) ? bias2 : bias3;
                    float2 bv = *(const float2*)&bptr[within];
                    c0 = tf32r(c0 + bv.x); c1 = tf32r(c1 + bv.y);
                    int b_ = row >> 11, s_ = row & 2047;
                    int h_ = within >> 6, d_ = within & 63;
                    size_t o = (size_t)t_ * (MROWS * DMODEL) +
                               (((size_t)(b_ * NHEADS + h_) * SEQ + s_) << 6) + d_;
                    *(float2*)&C[o] = make_float2(c0, c1);
                } else {
                    float2 bv = *(const float2*)&bias[col];
                    c0 += bv.x; c1 += bv.y;
                    if (epi == EPI_RELU) {
                        c0 = tf32r(fmaxf(c0, 0.f));
                        c1 = tf32r(fmaxf(c1, 0.f));
                    } else if (epi == EPI_RES) {
                        float2 r2 = *(const float2*)&res[(size_t)row * N + col];
                        c0 += r2.x; c1 += r2.y;
                    }
                    *(float2*)&C[(size_t)row * N + col] = make_float2(c0, c1);
                }
            }
        }
    }
}

// =====================================================================
// tf32 mma.sync flash attention (unchanged from R6/R7 WIN)
// =====================================================================
#define QS 68
#define KS 68
#define VS 72
#define PS 68
#define NKV 32
#define ATT_SQ   (128*QS)
#define ATT_SK   (64*KS)
#define ATT_SV   (64*VS)
#define ATT_SP   (128*PS)
#define ATTN_SMEM_BYTES ((ATT_SQ + 2*ATT_SK + 2*ATT_SV + ATT_SP)*4 + 2*64*4)

__global__ void __launch_bounds__(256) attn_mma_kernel(
    const float* __restrict__ Q, const float* __restrict__ K,
    const float* __restrict__ V, const int* __restrict__ mask,
    float* __restrict__ ctx)
{
    extern __shared__ float smf[];
    float* sQ = smf;
    float* sK = sQ + ATT_SQ;
    float* sV = sK + 2 * ATT_SK;
    float* sP = sV + 2 * ATT_SV;
    int*   sM = (int*)(sP + ATT_SP);

    int tid = threadIdx.x;
    int wid = tid >> 5, lane = tid & 31;
    int g = lane >> 2, q = lane & 3;
    int bh = blockIdx.y;
    int q0 = blockIdx.x * 128;
    int b  = bh / NHEADS;
    int h  = bh % NHEADS;

    const float* Qh = Q + (size_t)bh * SEQ * DK;
    const float* Kh = K + (size_t)bh * SEQ * DK;
    const float* Vh = V + (size_t)bh * SEQ * DK;
    const int* mrow = mask + b * SEQ;

    #pragma unroll
    for (int i = 0; i < 8; i++) {
        int c = tid + 256 * i;
        int r = c >> 4, c4 = (c & 15) << 2;
        *(float4*)&sQ[r * QS + c4] =
            *(const float4*)&Qh[(size_t)(q0 + r) * DK + c4];
    }

    auto loadKV = [&](int buf, int kv0) {
        #pragma unroll
        for (int i = 0; i < 4; i++) {
            int c = tid + 256 * i;
            int r = c >> 4, c4 = (c & 15) << 2;
            __pipeline_memcpy_async(&sK[buf * ATT_SK + r * KS + c4],
                                    &Kh[(size_t)(kv0 + r) * DK + c4], 16);
            __pipeline_memcpy_async(&sV[buf * ATT_SV + r * VS + c4],
                                    &Vh[(size_t)(kv0 + r) * DK + c4], 16);
        }
        if (tid < 64)
            __pipeline_memcpy_async(&sM[buf * 64 + tid], &mrow[kv0 + tid], 4);
    };

    loadKV(0, 0);
    __pipeline_commit();

    float m0 = -1e30f, m1 = -1e30f, l0 = 0.f, l1 = 0.f;
    float oacc[8][4];
    #pragma unroll
    for (int nt = 0; nt < 8; nt++)
        #pragma unroll
        for (int c = 0; c < 4; c++) oacc[nt][c] = 0.f;

    int wr0 = wid * 16;

    for (int t = 0; t < NKV; t++) {
        if (t + 1 < NKV) loadKV((t + 1) & 1, (t + 1) * 64);
        __pipeline_commit();
        __pipeline_wait_prior(1);
        __syncthreads();

        const float* bK = sK + (t & 1) * ATT_SK;
        const float* bV = sV + (t & 1) * ATT_SV;
        const int*   bM = sM + (t & 1) * 64;

        float sacc[8][4];
        #pragma unroll
        for (int nt = 0; nt < 8; nt++)
            #pragma unroll
            for (int c = 0; c < 4; c++) sacc[nt][c] = 0.f;

        #pragma unroll
        for (int kk = 0; kk < DK; kk += 8) {
            const float* ap = sQ + (wr0 + g) * QS + kk + q;
            uint32_t a0 = __float_as_uint(ap[0]);
            uint32_t a1 = __float_as_uint(ap[8 * QS]);
            uint32_t a2 = __float_as_uint(ap[4]);
            uint32_t a3 = __float_as_uint(ap[8 * QS + 4]);
            #pragma unroll
            for (int nt = 0; nt < 8; nt++) {
                const float* bp = bK + (nt * 8 + g) * KS + kk + q;
                mma_tf32(sacc[nt], a0, a1, a2, a3,
                         __float_as_uint(bp[0]), __float_as_uint(bp[4]));
            }
        }

        float mx0 = -1e30f, mx1 = -1e30f;
        #pragma unroll
        for (int nt = 0; nt < 8; nt++) {
            int c0i = nt * 8 + 2 * q;
            int mva = bM[c0i], mvb = bM[c0i + 1];
            sacc[nt][0] = mva ? sacc[nt][0] * 0.125f : NEGINF;
            sacc[nt][1] = mvb ? sacc[nt][1] * 0.125f : NEGINF;
            sacc[nt][2] = mva ? sacc[nt][2] * 0.125f : NEGINF;
            sacc[nt][3] = mvb ? sacc[nt][3] * 0.125f : NEGINF;
            mx0 = fmaxf(mx0, fmaxf(sacc[nt][0], sacc[nt][1]));
            mx1 = fmaxf(mx1, fmaxf(sacc[nt][2], sacc[nt][3]));
        }
        #pragma unroll
        for (int off = 1; off < 4; off <<= 1) {
            mx0 = fmaxf(mx0, __shfl_xor_sync(0xffffffffu, mx0, off));
            mx1 = fmaxf(mx1, __shfl_xor_sync(0xffffffffu, mx1, off));
        }
        float mn0 = fmaxf(m0, mx0), mn1 = fmaxf(m1, mx1);
        float cor0 = __expf(m0 - mn0), cor1 = __expf(m1 - mn1);
        float ls0 = 0.f, ls1 = 0.f;
        float* pr0 = sP + (wr0 + g) * PS;
        float* pr1 = pr0 + 8 * PS;
        #pragma unroll
        for (int nt = 0; nt < 8; nt++) {
            int c0i = nt * 8 + 2 * q;
            float p0 = __expf(sacc[nt][0] - mn0);
            float p1 = __expf(sacc[nt][1] - mn0);
            float p2 = __expf(sacc[nt][2] - mn1);
            float p3 = __expf(sacc[nt][3] - mn1);
            ls0 += p0 + p1; ls1 += p2 + p3;
            pr0[c0i]     = tf32r(p0);
            pr0[c0i + 1] = tf32r(p1);
            pr1[c0i]     = tf32r(p2);
            pr1[c0i + 1] = tf32r(p3);
        }
        #pragma unroll
        for (int off = 1; off < 4; off <<= 1) {
            ls0 += __shfl_xor_sync(0xffffffffu, ls0, off);
            ls1 += __shfl_xor_sync(0xffffffffu, ls1, off);
        }
        l0 = l0 * cor0 + ls0; m0 = mn0;
        l1 = l1 * cor1 + ls1; m1 = mn1;
        #pragma unroll
        for (int nt = 0; nt < 8; nt++) {
            oacc[nt][0] *= cor0; oacc[nt][1] *= cor0;
            oacc[nt][2] *= cor1; oacc[nt][3] *= cor1;
        }
        __syncwarp();

        #pragma unroll
        for (int kk = 0; kk < 64; kk += 8) {
            const float* ap = sP + (wr0 + g) * PS + kk + q;
            uint32_t a0 = __float_as_uint(ap[0]);
            uint32_t a1 = __float_as_uint(ap[8 * PS]);
            uint32_t a2 = __float_as_uint(ap[4]);
            uint32_t a3 = __float_as_uint(ap[8 * PS + 4]);
            #pragma unroll
            for (int nt = 0; nt < 8; nt++) {
                const float* bp = bV + (kk + q) * VS + nt * 8 + g;
                mma_tf32(oacc[nt], a0, a1, a2, a3,
                         __float_as_uint(bp[0]), __float_as_uint(bp[4 * VS]));
            }
        }
        __syncthreads();
    }

    float inv0 = 1.0f / l0, inv1 = 1.0f / l1;
    size_t row0 = (size_t)(b * SEQ + q0 + wr0 + g);
    size_t row1 = row0 + 8;
    #pragma unroll
    for (int nt = 0; nt < 8; nt++) {
        int col = h * DK + nt * 8 + 2 * q;
        *(float2*)&ctx[row0 * DMODEL + col] =
            make_float2(tf32r(oacc[nt][0] * inv0), tf32r(oacc[nt][1] * inv0));
        *(float2*)&ctx[row1 * DMODEL + col] =
            make_float2(tf32r(oacc[nt][2] * inv1), tf32r(oacc[nt][3] * inv1));
    }
}

// =====================================================================
// launcher
// =====================================================================
extern "C" void kernel_launch(void* const* d_in, const int* in_sizes, int n_in,
                              void* d_out, int out_size)
{
    const float* x    = (const float*)d_in[0];
    const int*   mask = (const int*)  d_in[1];
    const float* wq = (const float*)d_in[2],  *bq = (const float*)d_in[3];
    const float* wk = (const float*)d_in[4],  *bk = (const float*)d_in[5];
    const float* wv = (const float*)d_in[6],  *bv = (const float*)d_in[7];
    const float* wo = (const float*)d_in[8],  *bo = (const float*)d_in[9];
    const float* w1 = (const float*)d_in[10], *b1 = (const float*)d_in[11];
    const float* w2 = (const float*)d_in[12], *b2 = (const float*)d_in[13];
    const float* ln1a = (const float*)d_in[14], *ln1b = (const float*)d_in[15];
    const float* ln2a = (const float*)d_in[16], *ln2b = (const float*)d_in[17];
    float* out = (float*)d_out;

    float *xn, *qkv, *ctx, *x2, *hbuf;
    float *wqkv, *wor, *w1r, *w2r;
    cudaGetSymbolAddress((void**)&xn,   g_xn);
    cudaGetSymbolAddress((void**)&qkv,  g_qkv);
    cudaGetSymbolAddress((void**)&ctx,  g_ctx);
    cudaGetSymbolAddress((void**)&x2,   g_x2);
    cudaGetSymbolAddress((void**)&hbuf, g_h);
    cudaGetSymbolAddress((void**)&wqkv, g_wqkv);
    cudaGetSymbolAddress((void**)&wor,  g_wor);
    cudaGetSymbolAddress((void**)&w1r,  g_w1r);
    cudaGetSymbolAddress((void**)&w2r,  g_w2r);

    cudaFuncSetAttribute(attn_mma_kernel,
                         cudaFuncAttributeMaxDynamicSharedMemorySize,
                         ATTN_SMEM_BYTES);
    cudaFuncSetAttribute(mma_gemm_kernel,
                         cudaFuncAttributeMaxDynamicSharedMemorySize,
                         GEMM_SMEM);

    int n1 = DMODEL * DMODEL / 4, n2 = DMODEL * DFF / 4;
    trunc_qkv_kernel<<<(n1 + 255) / 256, 256>>>(wq, wk, wv, wqkv);
    trunc_kernel<<<(n1 + 255) / 256, 256>>>(wo, wor, n1);
    trunc_kernel<<<(n2 + 255) / 256, 256>>>(w1, w1r, n2);
    trunc_kernel<<<(n2 + 255) / 256, 256>>>(w2, w2r, n2);

    dim3 gQKV(3 * DMODEL / BN, MROWS / BM);   // (18, 64) = 1152 CTAs
    dim3 g768 (DMODEL / BN, MROWS / BM);      // (6, 64)
    dim3 g3072(DFF    / BN, MROWS / BM);      // (24, 64)

    float* qp = qkv;
    float* kp = qkv + (size_t)MROWS * DMODEL;
    float* vp = qkv + 2 * (size_t)MROWS * DMODEL;

    // sublayer 1
    ln_kernel<<<MROWS / 8, 256>>>(x, xn, ln1a, ln1b);
    mma_gemm_kernel<<<gQKV, 128, GEMM_SMEM>>>(xn, wqkv, bq, bk, bv, nullptr,
                                              qkv, MROWS, 3 * DMODEL, DMODEL, EPI_QKV3);
    attn_mma_kernel<<<dim3(SEQ / 128, BATCH * NHEADS), 256, ATTN_SMEM_BYTES>>>(qp, kp, vp, mask, ctx);
    mma_gemm_kernel<<<g768, 128, GEMM_SMEM>>>(ctx, wor, bo, nullptr, nullptr, x,
                                              x2, MROWS, DMODEL, DMODEL, EPI_RES);

    // sublayer 2
    ln_kernel<<<MROWS / 8, 256>>>(x2, xn, ln2a, ln2b);
    mma_gemm_kernel<<<g3072, 128, GEMM_SMEM>>>(xn, w1r, b1, nullptr, nullptr, nullptr,
                                               hbuf, MROWS, DFF, DMODEL, EPI_RELU);
    mma_gemm_kernel<<<g768, 128, GEMM_SMEM>>>(hbuf, w2r, b2, nullptr, nullptr, x2,
                                              out, MROWS, DMODEL, DFF, EPI_RES);
}